// round 1
// baseline (speedup 1.0000x reference)
#include <cuda_runtime.h>
#include <math.h>

#define BATCH 4
#define SEQ   2048
#define CDIM  1024
#define NHEAD 16
#define DHEAD 64
#define MR    (BATCH*SEQ)   /* 8192 rows */

// Scratch (device globals; no allocation allowed)
__device__ float g_q[(size_t)BATCH*NHEAD*SEQ*DHEAD];
__device__ float g_k[(size_t)BATCH*NHEAD*SEQ*DHEAD];
__device__ float g_v[(size_t)BATCH*NHEAD*SEQ*DHEAD];
__device__ float g_attn[(size_t)MR*CDIM];
__device__ float g_l[BATCH*NHEAD*SEQ];

// ---------------------------------------------------------------------------
// SGEMM: C = A[M,1024] @ W[1024,1024] + bias.  128x128 tile, TK=8, 8x8 micro.
// mode 0: plain row-major store.  mode 1: store into [B, NHEAD, T, DHEAD].
// ---------------------------------------------------------------------------
__global__ __launch_bounds__(256)
void sgemm_bias(const float* __restrict__ A, const float* __restrict__ W,
                const float* __restrict__ bias, float* __restrict__ O, int mode)
{
    __shared__ float As[8][128];   // [k][row]  (transposed A tile)
    __shared__ float Bs[8][128];   // [k][col]

    const int tid  = threadIdx.x;
    const int bm   = blockIdx.y << 7;
    const int bn   = blockIdx.x << 7;
    const int arow = tid >> 1,  acol = (tid & 1) << 2;
    const int brow = tid >> 5,  bcol = (tid & 31) << 2;
    const int row0 = (tid >> 4) << 3, col0 = (tid & 15) << 3;

    float acc[8][8] = {};

    for (int k0 = 0; k0 < CDIM; k0 += 8) {
        float4 av = *(const float4*)(A + (size_t)(bm + arow)*CDIM + k0 + acol);
        float4 bv = *(const float4*)(W + (size_t)(k0 + brow)*CDIM + bn + bcol);
        As[acol + 0][arow] = av.x;
        As[acol + 1][arow] = av.y;
        As[acol + 2][arow] = av.z;
        As[acol + 3][arow] = av.w;
        *(float4*)&Bs[brow][bcol] = bv;
        __syncthreads();

        #pragma unroll
        for (int k = 0; k < 8; k++) {
            float ar[8], br[8];
            *(float4*)(ar)     = *(const float4*)&As[k][row0];
            *(float4*)(ar + 4) = *(const float4*)&As[k][row0 + 4];
            *(float4*)(br)     = *(const float4*)&Bs[k][col0];
            *(float4*)(br + 4) = *(const float4*)&Bs[k][col0 + 4];
            #pragma unroll
            for (int i = 0; i < 8; i++)
                #pragma unroll
                for (int j = 0; j < 8; j++)
                    acc[i][j] += ar[i] * br[j];
        }
        __syncthreads();
    }

    #pragma unroll
    for (int i = 0; i < 8; i++) {
        int m  = bm + row0 + i;
        int bb = m >> 11, t = m & (SEQ - 1);
        #pragma unroll
        for (int j = 0; j < 8; j++) {
            int cn = bn + col0 + j;
            float val = acc[i][j] + bias[cn];
            if (mode == 0) {
                O[(size_t)m*CDIM + cn] = val;
            } else {
                int h = cn >> 6, d = cn & 63;
                O[((((size_t)bb*NHEAD + h)*SEQ + t) << 6) + d] = val;
            }
        }
    }
}

// ---------------------------------------------------------------------------
// attn_scores: per (head, 64-query-tile) block. Computes exp(QK^T/8) causal,
// writes unnormalized weights, accumulates row sums into g_l.
// exp without max-subtraction is safe: scores ~ N(0,1), |s| < ~6.
// ---------------------------------------------------------------------------
__global__ __launch_bounds__(256)
void attn_scores(const float* __restrict__ q, const float* __restrict__ k,
                 float* __restrict__ wts, float* __restrict__ l)
{
    __shared__ float Qst[64][68];   // [kk][row]
    __shared__ float Kst[64][68];   // [kk][col] during compute; [row][col] staging
    __shared__ float red[64][17];

    const int tid = threadIdx.x;
    const int bid = blockIdx.x;
    const int qt  = (SEQ/64 - 1) - (bid & 31);   // heavy tiles first
    const int hn  = bid >> 5;                    // b*NHEAD + n
    const int q0  = qt << 6;

    const float* qh = q + (size_t)hn * SEQ * DHEAD;
    const float* kh = k + (size_t)hn * SEQ * DHEAD;
    float* wrow = wts + (size_t)hn * SEQ * SEQ;

    for (int i = tid; i < 64*64; i += 256) {
        int r = i >> 6, c = i & 63;
        Qst[c][r] = qh[(size_t)(q0 + r)*DHEAD + c];
    }

    const int row0 = (tid >> 4) << 2;
    const int col0 = (tid & 15) << 2;
    float psum[4] = {0.f, 0.f, 0.f, 0.f};

    for (int kt = 0; kt <= qt; kt++) {
        __syncthreads();
        for (int i = tid; i < 64*64; i += 256) {
            int r = i >> 6, c = i & 63;
            Kst[c][r] = kh[(size_t)((kt << 6) + r)*DHEAD + c];
        }
        __syncthreads();

        float acc[4][4] = {};
        #pragma unroll 16
        for (int kk = 0; kk < 64; kk++) {
            float qa[4], kb[4];
            *(float4*)qa = *(const float4*)&Qst[kk][row0];
            *(float4*)kb = *(const float4*)&Kst[kk][col0];
            #pragma unroll
            for (int i = 0; i < 4; i++)
                #pragma unroll
                for (int j = 0; j < 4; j++)
                    acc[i][j] += qa[i] * kb[j];
        }

        float p[4][4];
        #pragma unroll
        for (int i = 0; i < 4; i++) {
            int grow = q0 + row0 + i;
            #pragma unroll
            for (int j = 0; j < 4; j++) {
                int gcol = (kt << 6) + col0 + j;
                p[i][j] = (gcol <= grow) ? __expf(acc[i][j] * 0.125f) : 0.f;
                psum[i] += p[i][j];
            }
        }

        // stage tile in smem for coalesced gmem write (reuse Kst)
        __syncthreads();
        float (*Ws)[68] = Kst;
        #pragma unroll
        for (int i = 0; i < 4; i++)
            #pragma unroll
            for (int j = 0; j < 4; j++)
                Ws[row0 + i][col0 + j] = p[i][j];
        __syncthreads();
        for (int i = tid; i < 64*64; i += 256) {
            int r = i >> 6, c = i & 63;
            wrow[(size_t)(q0 + r)*SEQ + (kt << 6) + c] = Ws[r][c];
        }
    }

    // zero upper-triangle tiles (d_out is poisoned)
    const int c0 = (qt + 1) << 6;
    const int w  = SEQ - c0;
    if (w > 0) {
        for (int i = tid; i < 64*w; i += 256) {
            int r = i / w, c = c0 + (i - r*w);
            wrow[(size_t)(q0 + r)*SEQ + c] = 0.f;
        }
    }

    // per-row sum reduction (deterministic, no atomics)
    #pragma unroll
    for (int i = 0; i < 4; i++) red[row0 + i][tid & 15] = psum[i];
    __syncthreads();
    if (tid < 64) {
        float s = 0.f;
        #pragma unroll
        for (int j = 0; j < 16; j++) s += red[tid][j];
        l[hn*SEQ + q0 + tid] = s;
    }
}

// ---------------------------------------------------------------------------
// attn_pv: normalizes weights in-place (scale by 1/rowsum) and computes
// O = P @ V, stored into [B, T, C] layout for the final projection.
// ---------------------------------------------------------------------------
__global__ __launch_bounds__(256)
void attn_pv(const float* __restrict__ v, float* __restrict__ wts,
             const float* __restrict__ l, float* __restrict__ attn)
{
    __shared__ float Pst[64][68];  // [f][row]
    __shared__ float Vs[64][68];   // [f][col]
    __shared__ float linv[64];

    const int tid = threadIdx.x;
    const int bid = blockIdx.x;
    const int qt  = (SEQ/64 - 1) - (bid & 31);
    const int hn  = bid >> 5;
    const int b   = hn >> 4, n = hn & 15;
    const int q0  = qt << 6;

    const float* vh = v + (size_t)hn * SEQ * DHEAD;
    float* wrow = wts + (size_t)hn * SEQ * SEQ;

    if (tid < 64) linv[tid] = 1.f / l[hn*SEQ + q0 + tid];

    const int row0 = (tid >> 4) << 2;
    const int col0 = (tid & 15) << 2;
    float acc[4][4] = {};

    for (int kt = 0; kt <= qt; kt++) {
        __syncthreads();   // also covers initial linv visibility
        for (int i = tid; i < 64*64; i += 256) {
            int r = i >> 6, c = i & 63;
            size_t widx = (size_t)(q0 + r)*SEQ + (kt << 6) + c;
            float p = wrow[widx] * linv[r];
            Pst[c][r]  = p;
            wrow[widx] = p;                       // normalized write-back
            Vs[r][c]   = vh[(size_t)((kt << 6) + r)*DHEAD + c];
        }
        __syncthreads();

        #pragma unroll 16
        for (int f = 0; f < 64; f++) {
            float pa[4], vb[4];
            *(float4*)pa = *(const float4*)&Pst[f][row0];
            *(float4*)vb = *(const float4*)&Vs[f][col0];
            #pragma unroll
            for (int i = 0; i < 4; i++)
                #pragma unroll
                for (int j = 0; j < 4; j++)
                    acc[i][j] += pa[i] * vb[j];
        }
    }

    #pragma unroll
    for (int i = 0; i < 4; i++)
        #pragma unroll
        for (int j = 0; j < 4; j++)
            attn[(size_t)(b*SEQ + q0 + row0 + i)*CDIM + (n << 6) + col0 + j] = acc[i][j];
}

// ---------------------------------------------------------------------------
extern "C" void kernel_launch(void* const* d_in, const int* in_sizes, int n_in,
                              void* d_out, int out_size)
{
    const float* x  = (const float*)d_in[0];
    const float* Wq = (const float*)d_in[1];
    const float* bq = (const float*)d_in[2];
    const float* Wk = (const float*)d_in[3];
    const float* bk = (const float*)d_in[4];
    const float* Wv = (const float*)d_in[5];
    const float* bv = (const float*)d_in[6];
    const float* Wo = (const float*)d_in[7];
    const float* bo = (const float*)d_in[8];

    float* out = (float*)d_out;                       // (B,T,C) first
    float* wts = out + (size_t)MR * CDIM;             // then (B,N,T,T) weights

    void *pq, *pk, *pv, *pa, *pl;
    cudaGetSymbolAddress(&pq, g_q);
    cudaGetSymbolAddress(&pk, g_k);
    cudaGetSymbolAddress(&pv, g_v);
    cudaGetSymbolAddress(&pa, g_attn);
    cudaGetSymbolAddress(&pl, g_l);

    dim3 grid(CDIM/128, MR/128);   // (8, 64)
    sgemm_bias<<<grid, 256>>>(x, Wq, bq, (float*)pq, 1);
    sgemm_bias<<<grid, 256>>>(x, Wk, bk, (float*)pk, 1);
    sgemm_bias<<<grid, 256>>>(x, Wv, bv, (float*)pv, 1);

    const int ablocks = BATCH*NHEAD*(SEQ/64);  // 2048
    attn_scores<<<ablocks, 256>>>((const float*)pq, (const float*)pk, wts, (float*)pl);
    attn_pv<<<ablocks, 256>>>((const float*)pv, wts, (const float*)pl, (float*)pa);

    sgemm_bias<<<grid, 256>>>((const float*)pa, Wo, bo, out, 0);
}

// round 7
// speedup vs baseline: 1.1125x; 1.1125x over previous
#include <cuda_runtime.h>
#include <cuda_bf16.h>
#include <math.h>
#include <stdint.h>

#define BATCH 4
#define SEQ   2048
#define CDIM  1024
#define NHEAD 16
#define DHEAD 64
#define MR    (BATCH*SEQ)   /* 8192 rows */

// ---------------- scratch (device globals; no allocation allowed) ----------
__device__ float g_q[(size_t)MR*CDIM];
__device__ float g_k[(size_t)MR*CDIM];
__device__ float g_v[(size_t)MR*CDIM];
__device__ float g_attn[(size_t)MR*CDIM];
__device__ float g_l[BATCH*NHEAD*SEQ];
__device__ __nv_bfloat16 g_ahi[(size_t)MR*CDIM];
__device__ __nv_bfloat16 g_alo[(size_t)MR*CDIM];
__device__ __nv_bfloat16 g_whi[(size_t)4*CDIM*CDIM];   // W^T hi, 4 matrices
__device__ __nv_bfloat16 g_wlo[(size_t)4*CDIM*CDIM];   // W^T lo

// ---------------- PTX helpers ----------------------------------------------
static __device__ __forceinline__ uint32_t smem_u32(const void* p) {
    uint32_t a;
    asm("{ .reg .u64 t; cvta.to.shared.u64 t, %1; cvt.u32.u64 %0, t; }"
        : "=r"(a) : "l"(p));
    return a;
}
static __device__ __forceinline__ void cp_async16(uint32_t dst, const void* src) {
    asm volatile("cp.async.cg.shared.global [%0], [%1], 16;" :: "r"(dst), "l"(src) : "memory");
}
static __device__ __forceinline__ void cp_commit() {
    asm volatile("cp.async.commit_group;" ::: "memory");
}
template <int N> static __device__ __forceinline__ void cp_wait() {
    asm volatile("cp.async.wait_group %0;" :: "n"(N) : "memory");
}
static __device__ __forceinline__ void mma_bf16(float* c, const uint32_t* a, const uint32_t* b) {
    asm volatile(
        "mma.sync.aligned.m16n8k16.row.col.f32.bf16.bf16.f32 "
        "{%0,%1,%2,%3}, {%4,%5,%6,%7}, {%8,%9}, {%0,%1,%2,%3};"
        : "+f"(c[0]), "+f"(c[1]), "+f"(c[2]), "+f"(c[3])
        : "r"(a[0]), "r"(a[1]), "r"(a[2]), "r"(a[3]), "r"(b[0]), "r"(b[1]));
}

// ---------------- HMMA split-bf16 GEMM --------------------------------------
// O[M,1024] = A[M,1024] @ W[1024,1024] + bias.
// A as bf16 hi/lo row-major [M,K]; W transposed as bf16 hi/lo [N,K].
// CTA: 128x128 tile, 8 warps in 4(m) x 2(n); warp: 32x64; BK=32 double-buffered.
#define BK      32
#define LDA     40                    /* halves per row (32 + 8 pad) -> 80B   */
#define TILE_H  (128*LDA)             /* halves per tile buffer                */
#define TILE_B  (TILE_H*2)            /* 10240 bytes                           */
#define STAGE_B (4*TILE_B)            /* Ahi,Alo,Bhi,Blo = 40960 bytes         */
#define GSM_TOTAL (2*STAGE_B)         /* 81920 bytes                           */
#define NCHUNK  (CDIM/BK)             /* 32 */

static __device__ __forceinline__ void gemm_fill(
    uint32_t st, int chunk,
    const __nv_bfloat16* __restrict__ Ahi, const __nv_bfloat16* __restrict__ Alo,
    const __nv_bfloat16* __restrict__ Bhi, const __nv_bfloat16* __restrict__ Blo,
    int m0, int n0, int tid)
{
    const int k0 = chunk << 5;
    #pragma unroll
    for (int t = 0; t < 8; t++) {
        int i = tid + t * 256;            // 2048 x 16B transfers
        int tile = i >> 9;                // 0:Ahi 1:Alo 2:Bhi 3:Blo
        int idx  = i & 511;
        int r = idx >> 2, j = idx & 3;    // row, 16B-column
        const __nv_bfloat16* base =
            (tile == 0) ? Ahi : (tile == 1) ? Alo : (tile == 2) ? Bhi : Blo;
        int row = ((tile < 2) ? m0 : n0) + r;
        cp_async16(st + tile * TILE_B + r * (LDA*2) + j * 16,
                   base + (size_t)row * CDIM + k0 + (j << 3));
    }
    cp_commit();
}

__global__ void __launch_bounds__(256, 1)
gemm_hmma(const __nv_bfloat16* __restrict__ Ahi, const __nv_bfloat16* __restrict__ Alo,
          const __nv_bfloat16* __restrict__ Bhi, const __nv_bfloat16* __restrict__ Blo,
          const float* __restrict__ bias, float* __restrict__ O)
{
    extern __shared__ __nv_bfloat16 smem[];
    const uint32_t sb = smem_u32(smem);
    const int tid  = threadIdx.x;
    const int warp = tid >> 5;
    const int lane = tid & 31;
    const int wm   = warp & 3;            // 4 m-groups of 32 rows
    const int wn   = warp >> 2;           // 2 n-groups of 64 cols
    const int n0 = blockIdx.x << 7;
    const int m0 = blockIdx.y << 7;

    // smem half-index bases of this warp's region within a stage
    const int a_row0 = wm * 32;           // rows in A tiles
    const int b_col0 = wn * 64;           // rows in B tiles (N-dim)
    const int lr = lane >> 2;             // 0..7
    const int lc = (lane & 3) << 1;       // 0,2,4,6 (halves)

    float acc[2][8][4];
    #pragma unroll
    for (int mt = 0; mt < 2; mt++)
        #pragma unroll
        for (int nt = 0; nt < 8; nt++)
            #pragma unroll
            for (int r = 0; r < 4; r++) acc[mt][nt][r] = 0.f;

    gemm_fill(sb,           0, Ahi, Alo, Bhi, Blo, m0, n0, tid);
    gemm_fill(sb + STAGE_B, 1, Ahi, Alo, Bhi, Blo, m0, n0, tid);

    for (int c = 0; c < NCHUNK; c++) {
        const __nv_bfloat16* st = smem + (size_t)(c & 1) * (STAGE_B/2);
        if (c < NCHUNK - 1) cp_wait<1>(); else cp_wait<0>();
        __syncthreads();

        const __nv_bfloat16* sAhi = st;
        const __nv_bfloat16* sAlo = st + TILE_H;
        const __nv_bfloat16* sBhi = st + 2*TILE_H;
        const __nv_bfloat16* sBlo = st + 3*TILE_H;

        #pragma unroll
        for (int ks = 0; ks < 2; ks++) {
            const int kh = ks * 16;
            uint32_t fahi[2][4], falo[2][4];
            #pragma unroll
            for (int mt = 0; mt < 2; mt++) {
                const int r0 = a_row0 + mt*16 + lr;
                const __nv_bfloat16* p0 = sAhi + r0*LDA + kh + lc;
                const __nv_bfloat16* p1 = sAlo + r0*LDA + kh + lc;
                fahi[mt][0] = *(const uint32_t*)(p0);
                fahi[mt][1] = *(const uint32_t*)(p0 + 8*LDA);
                fahi[mt][2] = *(const uint32_t*)(p0 + 8);
                fahi[mt][3] = *(const uint32_t*)(p0 + 8*LDA + 8);
                falo[mt][0] = *(const uint32_t*)(p1);
                falo[mt][1] = *(const uint32_t*)(p1 + 8*LDA);
                falo[mt][2] = *(const uint32_t*)(p1 + 8);
                falo[mt][3] = *(const uint32_t*)(p1 + 8*LDA + 8);
            }
            #pragma unroll
            for (int nt = 0; nt < 8; nt++) {
                const int nr = b_col0 + nt*8 + lr;
                const __nv_bfloat16* q0 = sBhi + nr*LDA + kh + lc;
                const __nv_bfloat16* q1 = sBlo + nr*LDA + kh + lc;
                uint32_t fbhi[2], fblo[2];
                fbhi[0] = *(const uint32_t*)(q0);
                fbhi[1] = *(const uint32_t*)(q0 + 8);
                fblo[0] = *(const uint32_t*)(q1);
                fblo[1] = *(const uint32_t*)(q1 + 8);
                #pragma unroll
                for (int mt = 0; mt < 2; mt++) {
                    mma_bf16(acc[mt][nt], fahi[mt], fbhi);
                    mma_bf16(acc[mt][nt], fahi[mt], fblo);
                    mma_bf16(acc[mt][nt], falo[mt], fbhi);
                }
            }
        }
        __syncthreads();
        if (c + 2 < NCHUNK)
            gemm_fill(sb + (c & 1) * STAGE_B, c + 2, Ahi, Alo, Bhi, Blo, m0, n0, tid);
    }

    // epilogue: acc -> global with bias. Thread lane layout of m16n8k16 C:
    // c0,c1: row lr(+groups), cols lc..lc+1; c2,c3: row lr+8.
    #pragma unroll
    for (int mt = 0; mt < 2; mt++) {
        const int grow = m0 + wm*32 + mt*16 + lr;
        #pragma unroll
        for (int nt = 0; nt < 8; nt++) {
            const int gcol = n0 + wn*64 + nt*8 + lc;
            float2 v0, v1;
            v0.x = acc[mt][nt][0] + bias[gcol];
            v0.y = acc[mt][nt][1] + bias[gcol + 1];
            v1.x = acc[mt][nt][2] + bias[gcol];
            v1.y = acc[mt][nt][3] + bias[gcol + 1];
            *(float2*)(O + (size_t)grow * CDIM + gcol)       = v0;
            *(float2*)(O + (size_t)(grow + 8) * CDIM + gcol) = v1;
        }
    }
}

// ---------------- conversion kernels ---------------------------------------
__global__ void __launch_bounds__(256)
split_f32(const float* __restrict__ in, __nv_bfloat16* __restrict__ hi,
          __nv_bfloat16* __restrict__ lo)
{
    size_t i = (size_t)blockIdx.x * 256 + threadIdx.x;
    float4 v = ((const float4*)in)[i];
    float f[4] = {v.x, v.y, v.z, v.w};
    __nv_bfloat16 h[4], l[4];
    #pragma unroll
    for (int j = 0; j < 4; j++) {
        h[j] = __float2bfloat16(f[j]);
        l[j] = __float2bfloat16(f[j] - __bfloat162float(h[j]));
    }
    ((uint2*)hi)[i] = *(uint2*)h;
    ((uint2*)lo)[i] = *(uint2*)l;
}

// W[K,N] fp32 -> T[N,K] bf16 hi/lo (transpose + split)
__global__ void __launch_bounds__(256)
transpose_split(const float* __restrict__ W, __nv_bfloat16* __restrict__ Thi,
                __nv_bfloat16* __restrict__ Tlo)
{
    __shared__ float ts[32][33];
    const int tx = threadIdx.x & 31, ty = threadIdx.x >> 5;   // 32x8
    const int bx = blockIdx.x << 5;   // n tile
    const int by = blockIdx.y << 5;   // k tile
    #pragma unroll
    for (int dy = 0; dy < 4; dy++)
        ts[ty + dy * 8][tx] = W[(size_t)(by + ty + dy * 8) * CDIM + bx + tx];
    __syncthreads();
    #pragma unroll
    for (int dy = 0; dy < 4; dy++) {
        float v = ts[tx][ty + dy * 8];
        __nv_bfloat16 h = __float2bfloat16(v);
        __nv_bfloat16 l = __float2bfloat16(v - __bfloat162float(h));
        size_t o = (size_t)(bx + ty + dy * 8) * CDIM + by + tx;
        Thi[o] = h;
        Tlo[o] = l;
    }
}

// ---------------- attention (fp32 FFMA, stride-1024 row-major inputs) ------
__global__ __launch_bounds__(256)
void attn_scores(const float* __restrict__ q, const float* __restrict__ k,
                 float* __restrict__ wts, float* __restrict__ l)
{
    __shared__ float Qst[64][68];
    __shared__ float Kst[64][68];
    __shared__ float red[64][17];

    const int tid = threadIdx.x;
    const int bid = blockIdx.x;
    const int qt  = (SEQ/64 - 1) - (bid & 31);
    const int hn  = bid >> 5;
    const int b   = hn >> 4, n = hn & 15;
    const int q0  = qt << 6;

    const float* qh = q + (size_t)b * SEQ * CDIM + n * 64;
    const float* kh = k + (size_t)b * SEQ * CDIM + n * 64;
    float* wrow = wts + (size_t)hn * SEQ * SEQ;

    for (int i = tid; i < 64*64; i += 256) {
        int r = i >> 6, c = i & 63;
        Qst[c][r] = qh[(size_t)(q0 + r)*CDIM + c];
    }

    const int row0 = (tid >> 4) << 2;
    const int col0 = (tid & 15) << 2;
    float psum[4] = {0.f, 0.f, 0.f, 0.f};

    for (int kt = 0; kt <= qt; kt++) {
        __syncthreads();
        for (int i = tid; i < 64*64; i += 256) {
            int r = i >> 6, c = i & 63;
            Kst[c][r] = kh[(size_t)((kt << 6) + r)*CDIM + c];
        }
        __syncthreads();

        float acc[4][4] = {};
        #pragma unroll 16
        for (int kk = 0; kk < 64; kk++) {
            float qa[4], kb[4];
            *(float4*)qa = *(const float4*)&Qst[kk][row0];
            *(float4*)kb = *(const float4*)&Kst[kk][col0];
            #pragma unroll
            for (int i = 0; i < 4; i++)
                #pragma unroll
                for (int j = 0; j < 4; j++)
                    acc[i][j] += qa[i] * kb[j];
        }

        float p[4][4];
        #pragma unroll
        for (int i = 0; i < 4; i++) {
            int grow = q0 + row0 + i;
            #pragma unroll
            for (int j = 0; j < 4; j++) {
                int gcol = (kt << 6) + col0 + j;
                p[i][j] = (gcol <= grow) ? __expf(acc[i][j] * 0.125f) : 0.f;
                psum[i] += p[i][j];
            }
        }

        __syncthreads();
        float (*Ws)[68] = Kst;
        #pragma unroll
        for (int i = 0; i < 4; i++)
            #pragma unroll
            for (int j = 0; j < 4; j++)
                Ws[row0 + i][col0 + j] = p[i][j];
        __syncthreads();
        for (int i = tid; i < 64*64; i += 256) {
            int r = i >> 6, c = i & 63;
            wrow[(size_t)(q0 + r)*SEQ + (kt << 6) + c] = Ws[r][c];
        }
    }

    const int c0 = (qt + 1) << 6;
    const int w  = SEQ - c0;
    if (w > 0) {
        for (int i = tid; i < 64*w; i += 256) {
            int r = i / w, c = c0 + (i - r*w);
            wrow[(size_t)(q0 + r)*SEQ + c] = 0.f;
        }
    }

    #pragma unroll
    for (int i = 0; i < 4; i++) red[row0 + i][tid & 15] = psum[i];
    __syncthreads();
    if (tid < 64) {
        float s = 0.f;
        #pragma unroll
        for (int j = 0; j < 16; j++) s += red[tid][j];
        l[hn*SEQ + q0 + tid] = s;
    }
}

__global__ __launch_bounds__(256)
void attn_pv(const float* __restrict__ v, float* __restrict__ wts,
             const float* __restrict__ l, float* __restrict__ attn)
{
    __shared__ float Pst[64][68];
    __shared__ float Vs[64][68];
    __shared__ float linv[64];

    const int tid = threadIdx.x;
    const int bid = blockIdx.x;
    const int qt  = (SEQ/64 - 1) - (bid & 31);
    const int hn  = bid >> 5;
    const int b   = hn >> 4, n = hn & 15;
    const int q0  = qt << 6;

    const float* vh = v + (size_t)b * SEQ * CDIM + n * 64;
    float* wrow = wts + (size_t)hn * SEQ * SEQ;

    if (tid < 64) linv[tid] = 1.f / l[hn*SEQ + q0 + tid];

    const int row0 = (tid >> 4) << 2;
    const int col0 = (tid & 15) << 2;
    float acc[4][4] = {};

    for (int kt = 0; kt <= qt; kt++) {
        __syncthreads();
        for (int i = tid; i < 64*64; i += 256) {
            int r = i >> 6, c = i & 63;
            size_t widx = (size_t)(q0 + r)*SEQ + (kt << 6) + c;
            float p = wrow[widx] * linv[r];
            Pst[c][r]  = p;
            wrow[widx] = p;
            Vs[r][c]   = vh[(size_t)((kt << 6) + r)*CDIM + c];
        }
        __syncthreads();

        #pragma unroll 16
        for (int f = 0; f < 64; f++) {
            float pa[4], vb[4];
            *(float4*)pa = *(const float4*)&Pst[f][row0];
            *(float4*)vb = *(const float4*)&Vs[f][col0];
            #pragma unroll
            for (int i = 0; i < 4; i++)
                #pragma unroll
                for (int j = 0; j < 4; j++)
                    acc[i][j] += pa[i] * vb[j];
        }
    }

    #pragma unroll
    for (int i = 0; i < 4; i++)
        #pragma unroll
        for (int j = 0; j < 4; j++)
            attn[(size_t)(b*SEQ + q0 + row0 + i)*CDIM + (n << 6) + col0 + j] = acc[i][j];
}

// ---------------------------------------------------------------------------
extern "C" void kernel_launch(void* const* d_in, const int* in_sizes, int n_in,
                              void* d_out, int out_size)
{
    const float* x  = (const float*)d_in[0];
    const float* Wq = (const float*)d_in[1];
    const float* bq = (const float*)d_in[2];
    const float* Wk = (const float*)d_in[3];
    const float* bk = (const float*)d_in[4];
    const float* Wv = (const float*)d_in[5];
    const float* bv = (const float*)d_in[6];
    const float* Wo = (const float*)d_in[7];
    const float* bo = (const float*)d_in[8];

    float* out = (float*)d_out;                 // (B,T,C)
    float* wts = out + (size_t)MR * CDIM;       // (B,N,T,T)

    void *pq, *pk, *pv, *pa, *pl, *pahi, *palo, *pwhi, *pwlo;
    cudaGetSymbolAddress(&pq, g_q);
    cudaGetSymbolAddress(&pk, g_k);
    cudaGetSymbolAddress(&pv, g_v);
    cudaGetSymbolAddress(&pa, g_attn);
    cudaGetSymbolAddress(&pl, g_l);
    cudaGetSymbolAddress(&pahi, g_ahi);
    cudaGetSymbolAddress(&palo, g_alo);
    cudaGetSymbolAddress(&pwhi, g_whi);
    cudaGetSymbolAddress(&pwlo, g_wlo);

    __nv_bfloat16* ahi = (__nv_bfloat16*)pahi;
    __nv_bfloat16* alo = (__nv_bfloat16*)palo;
    __nv_bfloat16* whi = (__nv_bfloat16*)pwhi;
    __nv_bfloat16* wlo = (__nv_bfloat16*)pwlo;
    const size_t WSZ = (size_t)CDIM * CDIM;

    cudaFuncSetAttribute(gemm_hmma, cudaFuncAttributeMaxDynamicSharedMemorySize, GSM_TOTAL);

    // weight transpose+split and x split
    dim3 tgrid(CDIM/32, CDIM/32);
    transpose_split<<<tgrid, 256>>>(Wq, whi + 0*WSZ, wlo + 0*WSZ);
    transpose_split<<<tgrid, 256>>>(Wk, whi + 1*WSZ, wlo + 1*WSZ);
    transpose_split<<<tgrid, 256>>>(Wv, whi + 2*WSZ, wlo + 2*WSZ);
    transpose_split<<<tgrid, 256>>>(Wo, whi + 3*WSZ, wlo + 3*WSZ);
    split_f32<<<(int)((size_t)MR*CDIM/4/256), 256>>>(x, ahi, alo);

    // QKV projections (tensor core, HMMA)
    dim3 ggrid(CDIM/128, MR/128);   // (8, 64)
    gemm_hmma<<<ggrid, 256, GSM_TOTAL>>>(ahi, alo, whi + 0*WSZ, wlo + 0*WSZ, bq, (float*)pq);
    gemm_hmma<<<ggrid, 256, GSM_TOTAL>>>(ahi, alo, whi + 1*WSZ, wlo + 1*WSZ, bk, (float*)pk);
    gemm_hmma<<<ggrid, 256, GSM_TOTAL>>>(ahi, alo, whi + 2*WSZ, wlo + 2*WSZ, bv, (float*)pv);

    // attention
    const int ablocks = BATCH*NHEAD*(SEQ/64);  // 2048
    attn_scores<<<ablocks, 256>>>((const float*)pq, (const float*)pk, wts, (float*)pl);
    attn_pv<<<ablocks, 256>>>((const float*)pv, wts, (const float*)pl, (float*)pa);

    // output projection (tensor core, HMMA)
    split_f32<<<(int)((size_t)MR*CDIM/4/256), 256>>>((const float*)pa, ahi, alo);
    gemm_hmma<<<ggrid, 256, GSM_TOTAL>>>(ahi, alo, whi + 3*WSZ, wlo + 3*WSZ, bo, out);
}

// round 10
// speedup vs baseline: 2.2974x; 2.0650x over previous
#include <cuda_runtime.h>
#include <cuda_bf16.h>
#include <math.h>
#include <stdint.h>

#define BATCH 4
#define SEQ   2048
#define CDIM  1024
#define NHEAD 16
#define DHEAD 64
#define MR    (BATCH*SEQ)   /* 8192 rows */

// ---------------- scratch (device globals; no allocation allowed) ----------
__device__ float g_v[(size_t)MR*CDIM];
__device__ float g_l[BATCH*NHEAD*SEQ];
__device__ __nv_bfloat16 g_ahi[(size_t)MR*CDIM];
__device__ __nv_bfloat16 g_alo[(size_t)MR*CDIM];
__device__ __nv_bfloat16 g_whi[(size_t)4*CDIM*CDIM];   // W^T hi, 4 matrices
__device__ __nv_bfloat16 g_wlo[(size_t)4*CDIM*CDIM];   // W^T lo
__device__ __nv_bfloat16 g_qhi[(size_t)MR*CDIM];
__device__ __nv_bfloat16 g_qlo[(size_t)MR*CDIM];
__device__ __nv_bfloat16 g_khi[(size_t)MR*CDIM];
__device__ __nv_bfloat16 g_klo[(size_t)MR*CDIM];
__device__ __nv_bfloat16 g_vthi[(size_t)BATCH*NHEAD*DHEAD*SEQ];
__device__ __nv_bfloat16 g_vtlo[(size_t)BATCH*NHEAD*DHEAD*SEQ];

// ---------------- PTX helpers ----------------------------------------------
static __device__ __forceinline__ uint32_t smem_u32(const void* p) {
    uint32_t a;
    asm("{ .reg .u64 t; cvta.to.shared.u64 t, %1; cvt.u32.u64 %0, t; }"
        : "=r"(a) : "l"(p));
    return a;
}
static __device__ __forceinline__ void cp_async16(uint32_t dst, const void* src) {
    asm volatile("cp.async.cg.shared.global [%0], [%1], 16;" :: "r"(dst), "l"(src) : "memory");
}
static __device__ __forceinline__ void cp_commit() {
    asm volatile("cp.async.commit_group;" ::: "memory");
}
template <int N> static __device__ __forceinline__ void cp_wait() {
    asm volatile("cp.async.wait_group %0;" :: "n"(N) : "memory");
}
static __device__ __forceinline__ void mma_bf16(float* c, const uint32_t* a, const uint32_t* b) {
    asm volatile(
        "mma.sync.aligned.m16n8k16.row.col.f32.bf16.bf16.f32 "
        "{%0,%1,%2,%3}, {%4,%5,%6,%7}, {%8,%9}, {%0,%1,%2,%3};"
        : "+f"(c[0]), "+f"(c[1]), "+f"(c[2]), "+f"(c[3])
        : "r"(a[0]), "r"(a[1]), "r"(a[2]), "r"(a[3]), "r"(b[0]), "r"(b[1]));
}

// fast exp on the FMA pipe (no MUFU): range-reduce + deg-6 poly, rel err ~1e-7
static __device__ __forceinline__ float exp_fast(float x) {
    int ni = __float2int_rn(x * 1.4426950408889634f);
    if (ni < -126) ni = -126;
    float nf = (float)ni;
    float r = fmaf(nf, -6.93145752e-1f, x);
    r = fmaf(nf, -1.42860677e-6f, r);
    float p = 1.3888889e-3f;
    p = fmaf(p, r, 8.3333333e-3f);
    p = fmaf(p, r, 4.1666667e-2f);
    p = fmaf(p, r, 1.6666667e-1f);
    p = fmaf(p, r, 0.5f);
    p = fmaf(p, r, 1.0f);
    p = fmaf(p, r, 1.0f);
    return p * __int_as_float((ni + 127) << 23);
}

// ---------------- HMMA split-bf16 GEMM --------------------------------------
#define BK      32
#define LDA     40
#define TILE_H  (128*LDA)
#define TILE_B  (TILE_H*2)
#define STAGE_B (4*TILE_B)
#define GSM_TOTAL (2*STAGE_B)
#define NCHUNK  (CDIM/BK)

static __device__ __forceinline__ void gemm_fill(
    uint32_t st, int chunk,
    const __nv_bfloat16* __restrict__ Ahi, const __nv_bfloat16* __restrict__ Alo,
    const __nv_bfloat16* __restrict__ Bhi, const __nv_bfloat16* __restrict__ Blo,
    int m0, int n0, int tid)
{
    const int k0 = chunk << 5;
    #pragma unroll
    for (int t = 0; t < 8; t++) {
        int i = tid + t * 256;
        int tile = i >> 9;
        int idx  = i & 511;
        int r = idx >> 2, j = idx & 3;
        const __nv_bfloat16* base =
            (tile == 0) ? Ahi : (tile == 1) ? Alo : (tile == 2) ? Bhi : Blo;
        int row = ((tile < 2) ? m0 : n0) + r;
        cp_async16(st + tile * TILE_B + r * (LDA*2) + j * 16,
                   base + (size_t)row * CDIM + k0 + (j << 3));
    }
    cp_commit();
}

__global__ void __launch_bounds__(256, 1)
gemm_hmma(const __nv_bfloat16* __restrict__ Ahi, const __nv_bfloat16* __restrict__ Alo,
          const __nv_bfloat16* __restrict__ Bhi, const __nv_bfloat16* __restrict__ Blo,
          const float* __restrict__ bias, float* __restrict__ O,
          __nv_bfloat16* __restrict__ Ohi, __nv_bfloat16* __restrict__ Olo)
{
    extern __shared__ __nv_bfloat16 smem[];
    const uint32_t sb = smem_u32(smem);
    const int tid  = threadIdx.x;
    const int warp = tid >> 5;
    const int lane = tid & 31;
    const int wm   = warp & 3;
    const int wn   = warp >> 2;
    const int n0 = blockIdx.x << 7;
    const int m0 = blockIdx.y << 7;

    const int a_row0 = wm * 32;
    const int b_col0 = wn * 64;
    const int lr = lane >> 2;
    const int lc = (lane & 3) << 1;

    float acc[2][8][4];
    #pragma unroll
    for (int mt = 0; mt < 2; mt++)
        #pragma unroll
        for (int nt = 0; nt < 8; nt++)
            #pragma unroll
            for (int r = 0; r < 4; r++) acc[mt][nt][r] = 0.f;

    gemm_fill(sb,           0, Ahi, Alo, Bhi, Blo, m0, n0, tid);
    gemm_fill(sb + STAGE_B, 1, Ahi, Alo, Bhi, Blo, m0, n0, tid);

    for (int c = 0; c < NCHUNK; c++) {
        const __nv_bfloat16* st = smem + (size_t)(c & 1) * (STAGE_B/2);
        if (c < NCHUNK - 1) cp_wait<1>(); else cp_wait<0>();
        __syncthreads();

        const __nv_bfloat16* sAhi = st;
        const __nv_bfloat16* sAlo = st + TILE_H;
        const __nv_bfloat16* sBhi = st + 2*TILE_H;
        const __nv_bfloat16* sBlo = st + 3*TILE_H;

        #pragma unroll
        for (int ks = 0; ks < 2; ks++) {
            const int kh = ks * 16;
            uint32_t fahi[2][4], falo[2][4];
            #pragma unroll
            for (int mt = 0; mt < 2; mt++) {
                const int r0 = a_row0 + mt*16 + lr;
                const __nv_bfloat16* p0 = sAhi + r0*LDA + kh + lc;
                const __nv_bfloat16* p1 = sAlo + r0*LDA + kh + lc;
                fahi[mt][0] = *(const uint32_t*)(p0);
                fahi[mt][1] = *(const uint32_t*)(p0 + 8*LDA);
                fahi[mt][2] = *(const uint32_t*)(p0 + 8);
                fahi[mt][3] = *(const uint32_t*)(p0 + 8*LDA + 8);
                falo[mt][0] = *(const uint32_t*)(p1);
                falo[mt][1] = *(const uint32_t*)(p1 + 8*LDA);
                falo[mt][2] = *(const uint32_t*)(p1 + 8);
                falo[mt][3] = *(const uint32_t*)(p1 + 8*LDA + 8);
            }
            #pragma unroll
            for (int nt = 0; nt < 8; nt++) {
                const int nr = b_col0 + nt*8 + lr;
                const __nv_bfloat16* q0 = sBhi + nr*LDA + kh + lc;
                const __nv_bfloat16* q1 = sBlo + nr*LDA + kh + lc;
                uint32_t fbhi[2], fblo[2];
                fbhi[0] = *(const uint32_t*)(q0);
                fbhi[1] = *(const uint32_t*)(q0 + 8);
                fblo[0] = *(const uint32_t*)(q1);
                fblo[1] = *(const uint32_t*)(q1 + 8);
                #pragma unroll
                for (int mt = 0; mt < 2; mt++) {
                    mma_bf16(acc[mt][nt], fahi[mt], fbhi);
                    mma_bf16(acc[mt][nt], fahi[mt], fblo);
                    mma_bf16(acc[mt][nt], falo[mt], fbhi);
                }
            }
        }
        __syncthreads();
        if (c + 2 < NCHUNK)
            gemm_fill(sb + (c & 1) * STAGE_B, c + 2, Ahi, Alo, Bhi, Blo, m0, n0, tid);
    }

    #pragma unroll
    for (int mt = 0; mt < 2; mt++) {
        const int grow = m0 + wm*32 + mt*16 + lr;
        #pragma unroll
        for (int nt = 0; nt < 8; nt++) {
            const int gcol = n0 + wn*64 + nt*8 + lc;
            float v[4];
            v[0] = acc[mt][nt][0] + bias[gcol];
            v[1] = acc[mt][nt][1] + bias[gcol + 1];
            v[2] = acc[mt][nt][2] + bias[gcol];
            v[3] = acc[mt][nt][3] + bias[gcol + 1];
            if (O) {
                *(float2*)(O + (size_t)grow * CDIM + gcol)       = make_float2(v[0], v[1]);
                *(float2*)(O + (size_t)(grow + 8) * CDIM + gcol) = make_float2(v[2], v[3]);
            }
            if (Ohi) {
                __nv_bfloat16 h[4], l[4];
                #pragma unroll
                for (int z = 0; z < 4; z++) {
                    h[z] = __float2bfloat16(v[z]);
                    l[z] = __float2bfloat16(v[z] - __bfloat162float(h[z]));
                }
                *(__nv_bfloat162*)(Ohi + (size_t)grow*CDIM + gcol)     = *(__nv_bfloat162*)&h[0];
                *(__nv_bfloat162*)(Ohi + (size_t)(grow+8)*CDIM + gcol) = *(__nv_bfloat162*)&h[2];
                *(__nv_bfloat162*)(Olo + (size_t)grow*CDIM + gcol)     = *(__nv_bfloat162*)&l[0];
                *(__nv_bfloat162*)(Olo + (size_t)(grow+8)*CDIM + gcol) = *(__nv_bfloat162*)&l[2];
            }
        }
    }
}

// ---------------- conversion kernels ---------------------------------------
__global__ void __launch_bounds__(256)
split_f32(const float* __restrict__ in, __nv_bfloat16* __restrict__ hi,
          __nv_bfloat16* __restrict__ lo)
{
    size_t i = (size_t)blockIdx.x * 256 + threadIdx.x;
    float4 v = ((const float4*)in)[i];
    float f[4] = {v.x, v.y, v.z, v.w};
    __nv_bfloat16 h[4], l[4];
    #pragma unroll
    for (int j = 0; j < 4; j++) {
        h[j] = __float2bfloat16(f[j]);
        l[j] = __float2bfloat16(f[j] - __bfloat162float(h[j]));
    }
    ((uint2*)hi)[i] = *(uint2*)h;
    ((uint2*)lo)[i] = *(uint2*)l;
}

__global__ void __launch_bounds__(256)
transpose_split(const float* __restrict__ W, __nv_bfloat16* __restrict__ Thi,
                __nv_bfloat16* __restrict__ Tlo)
{
    __shared__ float ts[32][33];
    const int tx = threadIdx.x & 31, ty = threadIdx.x >> 5;
    const int bx = blockIdx.x << 5;
    const int by = blockIdx.y << 5;
    #pragma unroll
    for (int dy = 0; dy < 4; dy++)
        ts[ty + dy * 8][tx] = W[(size_t)(by + ty + dy * 8) * CDIM + bx + tx];
    __syncthreads();
    #pragma unroll
    for (int dy = 0; dy < 4; dy++) {
        float v = ts[tx][ty + dy * 8];
        __nv_bfloat16 h = __float2bfloat16(v);
        __nv_bfloat16 l = __float2bfloat16(v - __bfloat162float(h));
        size_t o = (size_t)(bx + ty + dy * 8) * CDIM + by + tx;
        Thi[o] = h;
        Tlo[o] = l;
    }
}

// v fp32 [ (b*2048+t), h*64+d ] -> vt bf16 hi/lo [hn][d][t]
__global__ void __launch_bounds__(256)
vt_split(const float* __restrict__ v, __nv_bfloat16* __restrict__ vthi,
         __nv_bfloat16* __restrict__ vtlo)
{
    __shared__ float ts[32][33];
    const int tx = threadIdx.x & 31, ty = threadIdx.x >> 5;
    const int t0 = blockIdx.x << 5;
    const int d0 = blockIdx.y << 5;
    const int hn = blockIdx.z;
    const int b = hn >> 4, h = hn & 15;
    #pragma unroll
    for (int k = 0; k < 4; k++)
        ts[ty + k*8][tx] = v[(size_t)(b*SEQ + t0 + ty + k*8) * CDIM + h*64 + d0 + tx];
    __syncthreads();
    #pragma unroll
    for (int k = 0; k < 4; k++) {
        float val = ts[tx][ty + k*8];
        __nv_bfloat16 hh = __float2bfloat16(val);
        __nv_bfloat16 ll = __float2bfloat16(val - __bfloat162float(hh));
        size_t o = ((size_t)hn * DHEAD + d0 + ty + k*8) * SEQ + t0 + tx;
        vthi[o] = hh;
        vtlo[o] = ll;
    }
}

// ---------------- HMMA attention: scores -----------------------------------
// CTA: 128 q-rows of one head; k-loop over 128-wide key tiles (causal).
#define SLD   72                       /* halves per row (64 + 8 pad)         */
#define STILE (128*SLD)                /* halves per tile                     */
#define SSM_TOTAL (6*STILE*2)          /* Qhi,Qlo + 2 stages of Khi,Klo       */

static __device__ __forceinline__ void sc_fill_tile(
    uint32_t dsth, uint32_t dstl,
    const __nv_bfloat16* __restrict__ srch, const __nv_bfloat16* __restrict__ srcl,
    int row0, int tid)
{
    #pragma unroll
    for (int t = 0; t < 8; t++) {
        int i = tid + t * 256;          // 2048 chunks
        int which = i >> 10;
        int e = i & 1023;
        int r = e >> 3, c8 = e & 7;
        const __nv_bfloat16* src = (which ? srcl : srch) + (size_t)(row0 + r)*CDIM + (c8 << 3);
        uint32_t dst = (which ? dstl : dsth) + (r*SLD + (c8 << 3)) * 2;
        cp_async16(dst, src);
    }
    cp_commit();
}

__global__ void __launch_bounds__(256, 1)
attn_scores_hmma(const __nv_bfloat16* __restrict__ qhi, const __nv_bfloat16* __restrict__ qlo,
                 const __nv_bfloat16* __restrict__ khi, const __nv_bfloat16* __restrict__ klo,
                 float* __restrict__ wts, float* __restrict__ l)
{
    extern __shared__ __nv_bfloat16 sm[];
    __shared__ float red[128][2];
    const uint32_t sb = smem_u32(sm);
    const int tid  = threadIdx.x;
    const int warp = tid >> 5;
    const int lane = tid & 31;
    const int wm = warp & 3, wn = warp >> 2;
    const int lr = lane >> 2, lc = (lane & 3) << 1;

    const int qt = 15 - (blockIdx.x & 15);
    const int hn = blockIdx.x >> 4;
    const int b = hn >> 4, h = hn & 15;
    const int q0 = qt << 7;

    const __nv_bfloat16* gqh = qhi + (size_t)b*SEQ*CDIM + h*64;
    const __nv_bfloat16* gql = qlo + (size_t)b*SEQ*CDIM + h*64;
    const __nv_bfloat16* gkh = khi + (size_t)b*SEQ*CDIM + h*64;
    const __nv_bfloat16* gkl = klo + (size_t)b*SEQ*CDIM + h*64;
    float* wrow = wts + (size_t)hn * SEQ * SEQ;

    const __nv_bfloat16* sQh = sm;
    const __nv_bfloat16* sQl = sm + STILE;
    const uint32_t kbase = sb + 2*STILE*2;

    // Q + K0 (group 0)
    {
        #pragma unroll
        for (int t = 0; t < 8; t++) {
            int i = tid + t * 256;
            int which = i >> 10, e = i & 1023;
            int r = e >> 3, c8 = e & 7;
            cp_async16(sb + (which ? STILE*2 : 0) + (r*SLD + (c8<<3))*2,
                       (which ? gql : gqh) + (size_t)(q0 + r)*CDIM + (c8<<3));
        }
        sc_fill_tile(kbase, kbase + STILE*2, gkh, gkl, 0, tid);  // commits
    }
    if (qt >= 1)
        sc_fill_tile(kbase + 2*STILE*2, kbase + 3*STILE*2, gkh, gkl, 128, tid);

    float psum[4] = {0.f, 0.f, 0.f, 0.f};

    for (int kt = 0; kt <= qt; kt++) {
        if (kt + 1 <= qt) cp_wait<1>(); else cp_wait<0>();
        __syncthreads();

        const __nv_bfloat16* Kh = sm + (2 + 2*(kt & 1)) * STILE;
        const __nv_bfloat16* Kl = Kh + STILE;

        float acc[2][8][4];
        #pragma unroll
        for (int mt = 0; mt < 2; mt++)
            #pragma unroll
            for (int nt = 0; nt < 8; nt++)
                #pragma unroll
                for (int r = 0; r < 4; r++) acc[mt][nt][r] = 0.f;

        #pragma unroll
        for (int ks = 0; ks < 4; ks++) {
            const int kh = ks * 16;
            uint32_t fahi[2][4], falo[2][4];
            #pragma unroll
            for (int mt = 0; mt < 2; mt++) {
                const int r0 = wm*32 + mt*16 + lr;
                const __nv_bfloat16* p0 = sQh + r0*SLD + kh + lc;
                const __nv_bfloat16* p1 = sQl + r0*SLD + kh + lc;
                fahi[mt][0] = *(const uint32_t*)(p0);
                fahi[mt][1] = *(const uint32_t*)(p0 + 8*SLD);
                fahi[mt][2] = *(const uint32_t*)(p0 + 8);
                fahi[mt][3] = *(const uint32_t*)(p0 + 8*SLD + 8);
                falo[mt][0] = *(const uint32_t*)(p1);
                falo[mt][1] = *(const uint32_t*)(p1 + 8*SLD);
                falo[mt][2] = *(const uint32_t*)(p1 + 8);
                falo[mt][3] = *(const uint32_t*)(p1 + 8*SLD + 8);
            }
            #pragma unroll
            for (int nt = 0; nt < 8; nt++) {
                const int nr = wn*64 + nt*8 + lr;
                const __nv_bfloat16* pk0 = Kh + nr*SLD + kh + lc;
                const __nv_bfloat16* pk1 = Kl + nr*SLD + kh + lc;
                uint32_t fbhi[2], fblo[2];
                fbhi[0] = *(const uint32_t*)(pk0);
                fbhi[1] = *(const uint32_t*)(pk0 + 8);
                fblo[0] = *(const uint32_t*)(pk1);
                fblo[1] = *(const uint32_t*)(pk1 + 8);
                #pragma unroll
                for (int mt = 0; mt < 2; mt++) {
                    mma_bf16(acc[mt][nt], fahi[mt], fbhi);
                    mma_bf16(acc[mt][nt], fahi[mt], fblo);
                    mma_bf16(acc[mt][nt], falo[mt], fbhi);
                }
            }
        }

        // epilogue: scale, mask, exp, rowsum, store
        #pragma unroll
        for (int mt = 0; mt < 2; mt++) {
            const int grow0 = q0 + wm*32 + mt*16 + lr;
            const int grow1 = grow0 + 8;
            #pragma unroll
            for (int nt = 0; nt < 8; nt++) {
                const int gcol = (kt << 7) + wn*64 + nt*8 + lc;
                float e00 = (gcol     <= grow0) ? exp_fast(acc[mt][nt][0] * 0.125f) : 0.f;
                float e01 = (gcol + 1 <= grow0) ? exp_fast(acc[mt][nt][1] * 0.125f) : 0.f;
                float e10 = (gcol     <= grow1) ? exp_fast(acc[mt][nt][2] * 0.125f) : 0.f;
                float e11 = (gcol + 1 <= grow1) ? exp_fast(acc[mt][nt][3] * 0.125f) : 0.f;
                psum[mt*2 + 0] += e00 + e01;
                psum[mt*2 + 1] += e10 + e11;
                *(float2*)(wrow + (size_t)grow0*SEQ + gcol) = make_float2(e00, e01);
                *(float2*)(wrow + (size_t)grow1*SEQ + gcol) = make_float2(e10, e11);
            }
        }

        __syncthreads();
        if (kt + 2 <= qt)
            sc_fill_tile(kbase + 2*(kt & 1)*STILE*2, kbase + (2*(kt & 1)+1)*STILE*2,
                         gkh, gkl, (kt + 2) << 7, tid);
    }

    // zero upper triangle
    {
        const int c0 = (qt + 1) << 7;
        const int w4 = (SEQ - c0) >> 2;
        if (w4 > 0) {
            float4 z = make_float4(0.f, 0.f, 0.f, 0.f);
            for (int i = tid; i < 128 * w4; i += 256) {
                int r = i / w4, c = (i - r*w4) << 2;
                *(float4*)(wrow + (size_t)(q0 + r)*SEQ + c0 + c) = z;
            }
        }
    }

    // row sums: reduce quad lanes, then across wn
    #pragma unroll
    for (int t = 0; t < 4; t++) {
        psum[t] += __shfl_xor_sync(0xffffffff, psum[t], 1);
        psum[t] += __shfl_xor_sync(0xffffffff, psum[t], 2);
    }
    if ((lane & 3) == 0) {
        #pragma unroll
        for (int t = 0; t < 4; t++)
            red[wm*32 + (t >> 1)*16 + (t & 1)*8 + lr][wn] = psum[t];
    }
    __syncthreads();
    if (tid < 128) l[hn*SEQ + q0 + tid] = red[tid][0] + red[tid][1];
}

// ---------------- HMMA attention: P @ V ------------------------------------
#define VLD   136                      /* halves per Vt row (128 + 8 pad)     */
#define VTILE (64*VLD)                 /* halves per tile                     */
#define PSM_TOTAL (4*VTILE*2)          /* 2 stages x (hi,lo)                  */

static __device__ __forceinline__ void pv_fill_tile(
    uint32_t dsth, uint32_t dstl,
    const __nv_bfloat16* __restrict__ srch, const __nv_bfloat16* __restrict__ srcl,
    int t0, int tid)
{
    #pragma unroll
    for (int t = 0; t < 8; t++) {
        int i = tid + t * 256;          // 2048 chunks: 64 rows x 16 chunks x hi/lo
        int which = i >> 10;
        int e = i & 1023;
        int d = e >> 4, c8 = e & 15;
        const __nv_bfloat16* src = (which ? srcl : srch) + (size_t)d*SEQ + t0 + (c8 << 3);
        uint32_t dst = (which ? dstl : dsth) + (d*VLD + (c8 << 3)) * 2;
        cp_async16(dst, src);
    }
    cp_commit();
}

__global__ void __launch_bounds__(256, 1)
attn_pv_hmma(const __nv_bfloat16* __restrict__ vthi, const __nv_bfloat16* __restrict__ vtlo,
             float* __restrict__ wts, const float* __restrict__ l,
             __nv_bfloat16* __restrict__ ohi, __nv_bfloat16* __restrict__ olo)
{
    extern __shared__ __nv_bfloat16 sm[];
    __shared__ float linv[128];
    const uint32_t sb = smem_u32(sm);
    const int tid  = threadIdx.x;
    const int warp = tid >> 5;
    const int lane = tid & 31;
    const int wm = warp & 3, wn = warp >> 2;
    const int lr = lane >> 2, lc = (lane & 3) << 1;

    const int qt = 15 - (blockIdx.x & 15);
    const int hn = blockIdx.x >> 4;
    const int b = hn >> 4, h = hn & 15;
    const int q0 = qt << 7;

    const __nv_bfloat16* gvh = vthi + (size_t)hn * DHEAD * SEQ;
    const __nv_bfloat16* gvl = vtlo + (size_t)hn * DHEAD * SEQ;
    float* wrow = wts + (size_t)hn * SEQ * SEQ;

    if (tid < 128) linv[tid] = 1.f / l[hn*SEQ + q0 + tid];

    pv_fill_tile(sb, sb + VTILE*2, gvh, gvl, 0, tid);
    if (qt >= 1) pv_fill_tile(sb + 2*VTILE*2, sb + 3*VTILE*2, gvh, gvl, 128, tid);

    // per-thread row scales (constant across kt)
    float li[2][2];
    float acc[2][4][4];
    #pragma unroll
    for (int mt = 0; mt < 2; mt++) {
        #pragma unroll
        for (int nt = 0; nt < 4; nt++)
            #pragma unroll
            for (int r = 0; r < 4; r++) acc[mt][nt][r] = 0.f;
    }

    for (int kt = 0; kt <= qt; kt++) {
        if (kt + 1 <= qt) cp_wait<1>(); else cp_wait<0>();
        __syncthreads();
        if (kt == 0) {
            #pragma unroll
            for (int mt = 0; mt < 2; mt++) {
                li[mt][0] = linv[wm*32 + mt*16 + lr];
                li[mt][1] = linv[wm*32 + mt*16 + lr + 8];
            }
        }

        const __nv_bfloat16* Vh = sm + 2*(kt & 1)*VTILE;
        const __nv_bfloat16* Vl = Vh + VTILE;

        #pragma unroll
        for (int ks = 0; ks < 8; ks++) {
            const int gk = (kt << 7) + ks*16;
            uint32_t fphi[2][4], fplo[2][4];
            #pragma unroll
            for (int mt = 0; mt < 2; mt++) {
                const int r0 = q0 + wm*32 + mt*16 + lr;
                float2 v00 = *(const float2*)(wrow + (size_t)r0*SEQ + gk + lc);
                float2 v01 = *(const float2*)(wrow + (size_t)r0*SEQ + gk + lc + 8);
                float2 v10 = *(const float2*)(wrow + (size_t)(r0+8)*SEQ + gk + lc);
                float2 v11 = *(const float2*)(wrow + (size_t)(r0+8)*SEQ + gk + lc + 8);
                v00.x *= li[mt][0]; v00.y *= li[mt][0];
                v01.x *= li[mt][0]; v01.y *= li[mt][0];
                v10.x *= li[mt][1]; v10.y *= li[mt][1];
                v11.x *= li[mt][1]; v11.y *= li[mt][1];
                if (wn == 0) {
                    *(float2*)(wrow + (size_t)r0*SEQ + gk + lc)       = v00;
                    *(float2*)(wrow + (size_t)r0*SEQ + gk + lc + 8)   = v01;
                    *(float2*)(wrow + (size_t)(r0+8)*SEQ + gk + lc)     = v10;
                    *(float2*)(wrow + (size_t)(r0+8)*SEQ + gk + lc + 8) = v11;
                }
                float fv[4][2] = {{v00.x, v00.y}, {v10.x, v10.y}, {v01.x, v01.y}, {v11.x, v11.y}};
                #pragma unroll
                for (int z = 0; z < 4; z++) {
                    __nv_bfloat16 h0 = __float2bfloat16(fv[z][0]);
                    __nv_bfloat16 h1 = __float2bfloat16(fv[z][1]);
                    __nv_bfloat16 l0 = __float2bfloat16(fv[z][0] - __bfloat162float(h0));
                    __nv_bfloat16 l1 = __float2bfloat16(fv[z][1] - __bfloat162float(h1));
                    __nv_bfloat162 ph = {h0, h1}, pl = {l0, l1};
                    fphi[mt][z] = *(uint32_t*)&ph;
                    fplo[mt][z] = *(uint32_t*)&pl;
                }
            }
            #pragma unroll
            for (int nt = 0; nt < 4; nt++) {
                const int nr = wn*32 + nt*8 + lr;
                const __nv_bfloat16* pv0 = Vh + nr*VLD + ks*16 + lc;
                const __nv_bfloat16* pv1 = Vl + nr*VLD + ks*16 + lc;
                uint32_t fbhi[2], fblo[2];
                fbhi[0] = *(const uint32_t*)(pv0);
                fbhi[1] = *(const uint32_t*)(pv0 + 8);
                fblo[0] = *(const uint32_t*)(pv1);
                fblo[1] = *(const uint32_t*)(pv1 + 8);
                #pragma unroll
                for (int mt = 0; mt < 2; mt++) {
                    mma_bf16(acc[mt][nt], fphi[mt], fbhi);
                    mma_bf16(acc[mt][nt], fphi[mt], fblo);
                    mma_bf16(acc[mt][nt], fplo[mt], fbhi);
                }
            }
        }

        __syncthreads();
        if (kt + 2 <= qt)
            pv_fill_tile(sb + 2*(kt & 1)*VTILE*2, sb + (2*(kt & 1)+1)*VTILE*2,
                         gvh, gvl, (kt + 2) << 7, tid);
    }

    // epilogue: write Wo-GEMM input (bf16 hi/lo split) at [(b*2048+t)][h*64+d]
    #pragma unroll
    for (int mt = 0; mt < 2; mt++) {
        const int grow = q0 + wm*32 + mt*16 + lr;
        #pragma unroll
        for (int nt = 0; nt < 4; nt++) {
            const int d = wn*32 + nt*8 + lc;
            const size_t o0 = (size_t)(b*SEQ + grow) * CDIM + h*64 + d;
            const size_t o1 = (size_t)(b*SEQ + grow + 8) * CDIM + h*64 + d;
            float v[4] = {acc[mt][nt][0], acc[mt][nt][1], acc[mt][nt][2], acc[mt][nt][3]};
            __nv_bfloat16 hh[4], ll[4];
            #pragma unroll
            for (int z = 0; z < 4; z++) {
                hh[z] = __float2bfloat16(v[z]);
                ll[z] = __float2bfloat16(v[z] - __bfloat162float(hh[z]));
            }
            *(__nv_bfloat162*)(ohi + o0) = *(__nv_bfloat162*)&hh[0];
            *(__nv_bfloat162*)(ohi + o1) = *(__nv_bfloat162*)&hh[2];
            *(__nv_bfloat162*)(olo + o0) = *(__nv_bfloat162*)&ll[0];
            *(__nv_bfloat162*)(olo + o1) = *(__nv_bfloat162*)&ll[2];
        }
    }
}

// ---------------------------------------------------------------------------
extern "C" void kernel_launch(void* const* d_in, const int* in_sizes, int n_in,
                              void* d_out, int out_size)
{
    const float* x  = (const float*)d_in[0];
    const float* Wq = (const float*)d_in[1];
    const float* bq = (const float*)d_in[2];
    const float* Wk = (const float*)d_in[3];
    const float* bk = (const float*)d_in[4];
    const float* Wv = (const float*)d_in[5];
    const float* bv = (const float*)d_in[6];
    const float* Wo = (const float*)d_in[7];
    const float* bo = (const float*)d_in[8];

    float* out = (float*)d_out;                 // (B,T,C)
    float* wts = out + (size_t)MR * CDIM;       // (B,N,T,T)

    void *pv, *pl, *pahi, *palo, *pwhi, *pwlo;
    void *pqhi, *pqlo, *pkhi, *pklo, *pvthi, *pvtlo;
    cudaGetSymbolAddress(&pv, g_v);
    cudaGetSymbolAddress(&pl, g_l);
    cudaGetSymbolAddress(&pahi, g_ahi);
    cudaGetSymbolAddress(&palo, g_alo);
    cudaGetSymbolAddress(&pwhi, g_whi);
    cudaGetSymbolAddress(&pwlo, g_wlo);
    cudaGetSymbolAddress(&pqhi, g_qhi);
    cudaGetSymbolAddress(&pqlo, g_qlo);
    cudaGetSymbolAddress(&pkhi, g_khi);
    cudaGetSymbolAddress(&pklo, g_klo);
    cudaGetSymbolAddress(&pvthi, g_vthi);
    cudaGetSymbolAddress(&pvtlo, g_vtlo);

    __nv_bfloat16* ahi = (__nv_bfloat16*)pahi;
    __nv_bfloat16* alo = (__nv_bfloat16*)palo;
    __nv_bfloat16* whi = (__nv_bfloat16*)pwhi;
    __nv_bfloat16* wlo = (__nv_bfloat16*)pwlo;
    const size_t WSZ = (size_t)CDIM * CDIM;

    cudaFuncSetAttribute(gemm_hmma, cudaFuncAttributeMaxDynamicSharedMemorySize, GSM_TOTAL);
    cudaFuncSetAttribute(attn_scores_hmma, cudaFuncAttributeMaxDynamicSharedMemorySize, SSM_TOTAL);
    cudaFuncSetAttribute(attn_pv_hmma, cudaFuncAttributeMaxDynamicSharedMemorySize, PSM_TOTAL);

    dim3 tgrid(CDIM/32, CDIM/32);
    transpose_split<<<tgrid, 256>>>(Wq, whi + 0*WSZ, wlo + 0*WSZ);
    transpose_split<<<tgrid, 256>>>(Wk, whi + 1*WSZ, wlo + 1*WSZ);
    transpose_split<<<tgrid, 256>>>(Wv, whi + 2*WSZ, wlo + 2*WSZ);
    transpose_split<<<tgrid, 256>>>(Wo, whi + 3*WSZ, wlo + 3*WSZ);
    split_f32<<<(int)((size_t)MR*CDIM/4/256), 256>>>(x, ahi, alo);

    dim3 ggrid(CDIM/128, MR/128);
    gemm_hmma<<<ggrid, 256, GSM_TOTAL>>>(ahi, alo, whi + 0*WSZ, wlo + 0*WSZ, bq,
                                          nullptr, (__nv_bfloat16*)pqhi, (__nv_bfloat16*)pqlo);
    gemm_hmma<<<ggrid, 256, GSM_TOTAL>>>(ahi, alo, whi + 1*WSZ, wlo + 1*WSZ, bk,
                                          nullptr, (__nv_bfloat16*)pkhi, (__nv_bfloat16*)pklo);
    gemm_hmma<<<ggrid, 256, GSM_TOTAL>>>(ahi, alo, whi + 2*WSZ, wlo + 2*WSZ, bv,
                                          (float*)pv, nullptr, nullptr);

    dim3 vgrid(SEQ/32, DHEAD/32, BATCH*NHEAD);
    vt_split<<<vgrid, 256>>>((const float*)pv, (__nv_bfloat16*)pvthi, (__nv_bfloat16*)pvtlo);

    const int ablocks = BATCH*NHEAD*(SEQ/128);  // 1024
    attn_scores_hmma<<<ablocks, 256, SSM_TOTAL>>>(
        (const __nv_bfloat16*)pqhi, (const __nv_bfloat16*)pqlo,
        (const __nv_bfloat16*)pkhi, (const __nv_bfloat16*)pklo, wts, (float*)pl);
    attn_pv_hmma<<<ablocks, 256, PSM_TOTAL>>>(
        (const __nv_bfloat16*)pvthi, (const __nv_bfloat16*)pvtlo,
        wts, (const float*)pl, ahi, alo);

    gemm_hmma<<<ggrid, 256, GSM_TOTAL>>>(ahi, alo, whi + 3*WSZ, wlo + 3*WSZ, bo,
                                          out, nullptr, nullptr);
}

// round 13
// speedup vs baseline: 2.5047x; 1.0903x over previous
#include <cuda_runtime.h>
#include <cuda_bf16.h>
#include <cuda_fp16.h>
#include <math.h>
#include <stdint.h>

#define BATCH 4
#define SEQ   2048
#define CDIM  1024
#define NHEAD 16
#define DHEAD 64
#define MR    (BATCH*SEQ)   /* 8192 rows */

// ---------------- scratch (device globals; no allocation allowed) ----------
__device__ float g_v[(size_t)MR*CDIM];
__device__ float g_l[BATCH*NHEAD*SEQ];
__device__ __half g_p[(size_t)BATCH*NHEAD*SEQ*SEQ];   // unnormalized exp(S), fp16
__device__ __nv_bfloat16 g_ahi[(size_t)MR*CDIM];
__device__ __nv_bfloat16 g_alo[(size_t)MR*CDIM];
__device__ __nv_bfloat16 g_whi[(size_t)4*CDIM*CDIM];   // W^T hi, 4 matrices
__device__ __nv_bfloat16 g_wlo[(size_t)4*CDIM*CDIM];   // W^T lo
__device__ __nv_bfloat16 g_qhi[(size_t)MR*CDIM];
__device__ __nv_bfloat16 g_qlo[(size_t)MR*CDIM];
__device__ __nv_bfloat16 g_khi[(size_t)MR*CDIM];
__device__ __nv_bfloat16 g_klo[(size_t)MR*CDIM];
__device__ __half g_vthi[(size_t)BATCH*NHEAD*DHEAD*SEQ];
__device__ __half g_vtlo[(size_t)BATCH*NHEAD*DHEAD*SEQ];

// ---------------- PTX helpers ----------------------------------------------
static __device__ __forceinline__ uint32_t smem_u32(const void* p) {
    uint32_t a;
    asm("{ .reg .u64 t; cvta.to.shared.u64 t, %1; cvt.u32.u64 %0, t; }"
        : "=r"(a) : "l"(p));
    return a;
}
static __device__ __forceinline__ void cp_async16(uint32_t dst, const void* src) {
    asm volatile("cp.async.cg.shared.global [%0], [%1], 16;" :: "r"(dst), "l"(src) : "memory");
}
static __device__ __forceinline__ void cp_commit() {
    asm volatile("cp.async.commit_group;" ::: "memory");
}
template <int N> static __device__ __forceinline__ void cp_wait() {
    asm volatile("cp.async.wait_group %0;" :: "n"(N) : "memory");
}
static __device__ __forceinline__ void mma_bf16(float* c, const uint32_t* a, const uint32_t* b) {
    asm volatile(
        "mma.sync.aligned.m16n8k16.row.col.f32.bf16.bf16.f32 "
        "{%0,%1,%2,%3}, {%4,%5,%6,%7}, {%8,%9}, {%0,%1,%2,%3};"
        : "+f"(c[0]), "+f"(c[1]), "+f"(c[2]), "+f"(c[3])
        : "r"(a[0]), "r"(a[1]), "r"(a[2]), "r"(a[3]), "r"(b[0]), "r"(b[1]));
}
static __device__ __forceinline__ void mma_f16(float* c, const uint32_t* a, const uint32_t* b) {
    asm volatile(
        "mma.sync.aligned.m16n8k16.row.col.f32.f16.f16.f32 "
        "{%0,%1,%2,%3}, {%4,%5,%6,%7}, {%8,%9}, {%0,%1,%2,%3};"
        : "+f"(c[0]), "+f"(c[1]), "+f"(c[2]), "+f"(c[3])
        : "r"(a[0]), "r"(a[1]), "r"(a[2]), "r"(a[3]), "r"(b[0]), "r"(b[1]));
}

// fast exp on the FMA pipe (no MUFU): range-reduce + deg-6 poly, rel err ~1e-7
static __device__ __forceinline__ float exp_fast(float x) {
    int ni = __float2int_rn(x * 1.4426950408889634f);
    if (ni < -126) ni = -126;
    float nf = (float)ni;
    float r = fmaf(nf, -6.93145752e-1f, x);
    r = fmaf(nf, -1.42860677e-6f, r);
    float p = 1.3888889e-3f;
    p = fmaf(p, r, 8.3333333e-3f);
    p = fmaf(p, r, 4.1666667e-2f);
    p = fmaf(p, r, 1.6666667e-1f);
    p = fmaf(p, r, 0.5f);
    p = fmaf(p, r, 1.0f);
    p = fmaf(p, r, 1.0f);
    return p * __int_as_float((ni + 127) << 23);
}

// ---------------- HMMA split-bf16 GEMM --------------------------------------
#define BK      32
#define LDA     40
#define TILE_H  (128*LDA)
#define TILE_B  (TILE_H*2)
#define STAGE_B (4*TILE_B)
#define GSM_TOTAL (2*STAGE_B)
#define NCHUNK  (CDIM/BK)

static __device__ __forceinline__ void gemm_fill(
    uint32_t st, int chunk,
    const __nv_bfloat16* __restrict__ Ahi, const __nv_bfloat16* __restrict__ Alo,
    const __nv_bfloat16* __restrict__ Bhi, const __nv_bfloat16* __restrict__ Blo,
    int m0, int n0, int tid)
{
    const int k0 = chunk << 5;
    #pragma unroll
    for (int t = 0; t < 8; t++) {
        int i = tid + t * 256;
        int tile = i >> 9;
        int idx  = i & 511;
        int r = idx >> 2, j = idx & 3;
        const __nv_bfloat16* base =
            (tile == 0) ? Ahi : (tile == 1) ? Alo : (tile == 2) ? Bhi : Blo;
        int row = ((tile < 2) ? m0 : n0) + r;
        cp_async16(st + tile * TILE_B + r * (LDA*2) + j * 16,
                   base + (size_t)row * CDIM + k0 + (j << 3));
    }
    cp_commit();
}

__global__ void __launch_bounds__(256, 1)
gemm_hmma(const __nv_bfloat16* __restrict__ Ahi, const __nv_bfloat16* __restrict__ Alo,
          const __nv_bfloat16* __restrict__ Bhi, const __nv_bfloat16* __restrict__ Blo,
          const float* __restrict__ bias, float* __restrict__ O,
          __nv_bfloat16* __restrict__ Ohi, __nv_bfloat16* __restrict__ Olo)
{
    extern __shared__ __nv_bfloat16 smem[];
    const uint32_t sb = smem_u32(smem);
    const int tid  = threadIdx.x;
    const int warp = tid >> 5;
    const int lane = tid & 31;
    const int wm   = warp & 3;
    const int wn   = warp >> 2;
    const int n0 = blockIdx.x << 7;
    const int m0 = blockIdx.y << 7;

    const int a_row0 = wm * 32;
    const int b_col0 = wn * 64;
    const int lr = lane >> 2;
    const int lc = (lane & 3) << 1;

    float acc[2][8][4];
    #pragma unroll
    for (int mt = 0; mt < 2; mt++)
        #pragma unroll
        for (int nt = 0; nt < 8; nt++)
            #pragma unroll
            for (int r = 0; r < 4; r++) acc[mt][nt][r] = 0.f;

    gemm_fill(sb,           0, Ahi, Alo, Bhi, Blo, m0, n0, tid);
    gemm_fill(sb + STAGE_B, 1, Ahi, Alo, Bhi, Blo, m0, n0, tid);

    for (int c = 0; c < NCHUNK; c++) {
        const __nv_bfloat16* st = smem + (size_t)(c & 1) * (STAGE_B/2);
        if (c < NCHUNK - 1) cp_wait<1>(); else cp_wait<0>();
        __syncthreads();

        const __nv_bfloat16* sAhi = st;
        const __nv_bfloat16* sAlo = st + TILE_H;
        const __nv_bfloat16* sBhi = st + 2*TILE_H;
        const __nv_bfloat16* sBlo = st + 3*TILE_H;

        #pragma unroll
        for (int ks = 0; ks < 2; ks++) {
            const int kh = ks * 16;
            uint32_t fahi[2][4], falo[2][4];
            #pragma unroll
            for (int mt = 0; mt < 2; mt++) {
                const int r0 = a_row0 + mt*16 + lr;
                const __nv_bfloat16* p0 = sAhi + r0*LDA + kh + lc;
                const __nv_bfloat16* p1 = sAlo + r0*LDA + kh + lc;
                fahi[mt][0] = *(const uint32_t*)(p0);
                fahi[mt][1] = *(const uint32_t*)(p0 + 8*LDA);
                fahi[mt][2] = *(const uint32_t*)(p0 + 8);
                fahi[mt][3] = *(const uint32_t*)(p0 + 8*LDA + 8);
                falo[mt][0] = *(const uint32_t*)(p1);
                falo[mt][1] = *(const uint32_t*)(p1 + 8*LDA);
                falo[mt][2] = *(const uint32_t*)(p1 + 8);
                falo[mt][3] = *(const uint32_t*)(p1 + 8*LDA + 8);
            }
            #pragma unroll
            for (int nt = 0; nt < 8; nt++) {
                const int nr = b_col0 + nt*8 + lr;
                const __nv_bfloat16* q0 = sBhi + nr*LDA + kh + lc;
                const __nv_bfloat16* q1 = sBlo + nr*LDA + kh + lc;
                uint32_t fbhi[2], fblo[2];
                fbhi[0] = *(const uint32_t*)(q0);
                fbhi[1] = *(const uint32_t*)(q0 + 8);
                fblo[0] = *(const uint32_t*)(q1);
                fblo[1] = *(const uint32_t*)(q1 + 8);
                #pragma unroll
                for (int mt = 0; mt < 2; mt++) {
                    mma_bf16(acc[mt][nt], fahi[mt], fbhi);
                    mma_bf16(acc[mt][nt], fahi[mt], fblo);
                    mma_bf16(acc[mt][nt], falo[mt], fbhi);
                }
            }
        }
        __syncthreads();
        if (c + 2 < NCHUNK)
            gemm_fill(sb + (c & 1) * STAGE_B, c + 2, Ahi, Alo, Bhi, Blo, m0, n0, tid);
    }

    #pragma unroll
    for (int mt = 0; mt < 2; mt++) {
        const int grow = m0 + wm*32 + mt*16 + lr;
        #pragma unroll
        for (int nt = 0; nt < 8; nt++) {
            const int gcol = n0 + wn*64 + nt*8 + lc;
            float v[4];
            v[0] = acc[mt][nt][0] + bias[gcol];
            v[1] = acc[mt][nt][1] + bias[gcol + 1];
            v[2] = acc[mt][nt][2] + bias[gcol];
            v[3] = acc[mt][nt][3] + bias[gcol + 1];
            if (O) {
                *(float2*)(O + (size_t)grow * CDIM + gcol)       = make_float2(v[0], v[1]);
                *(float2*)(O + (size_t)(grow + 8) * CDIM + gcol) = make_float2(v[2], v[3]);
            }
            if (Ohi) {
                __nv_bfloat16 h[4], l[4];
                #pragma unroll
                for (int z = 0; z < 4; z++) {
                    h[z] = __float2bfloat16(v[z]);
                    l[z] = __float2bfloat16(v[z] - __bfloat162float(h[z]));
                }
                *(__nv_bfloat162*)(Ohi + (size_t)grow*CDIM + gcol)     = *(__nv_bfloat162*)&h[0];
                *(__nv_bfloat162*)(Ohi + (size_t)(grow+8)*CDIM + gcol) = *(__nv_bfloat162*)&h[2];
                *(__nv_bfloat162*)(Olo + (size_t)grow*CDIM + gcol)     = *(__nv_bfloat162*)&l[0];
                *(__nv_bfloat162*)(Olo + (size_t)(grow+8)*CDIM + gcol) = *(__nv_bfloat162*)&l[2];
            }
        }
    }
}

// ---------------- conversion kernels ---------------------------------------
__global__ void __launch_bounds__(256)
split_f32(const float* __restrict__ in, __nv_bfloat16* __restrict__ hi,
          __nv_bfloat16* __restrict__ lo)
{
    size_t i = (size_t)blockIdx.x * 256 + threadIdx.x;
    float4 v = ((const float4*)in)[i];
    float f[4] = {v.x, v.y, v.z, v.w};
    __nv_bfloat16 h[4], l[4];
    #pragma unroll
    for (int j = 0; j < 4; j++) {
        h[j] = __float2bfloat16(f[j]);
        l[j] = __float2bfloat16(f[j] - __bfloat162float(h[j]));
    }
    ((uint2*)hi)[i] = *(uint2*)h;
    ((uint2*)lo)[i] = *(uint2*)l;
}

__global__ void __launch_bounds__(256)
transpose_split(const float* __restrict__ W, __nv_bfloat16* __restrict__ Thi,
                __nv_bfloat16* __restrict__ Tlo)
{
    __shared__ float ts[32][33];
    const int tx = threadIdx.x & 31, ty = threadIdx.x >> 5;
    const int bx = blockIdx.x << 5;
    const int by = blockIdx.y << 5;
    #pragma unroll
    for (int dy = 0; dy < 4; dy++)
        ts[ty + dy * 8][tx] = W[(size_t)(by + ty + dy * 8) * CDIM + bx + tx];
    __syncthreads();
    #pragma unroll
    for (int dy = 0; dy < 4; dy++) {
        float v = ts[tx][ty + dy * 8];
        __nv_bfloat16 h = __float2bfloat16(v);
        __nv_bfloat16 l = __float2bfloat16(v - __bfloat162float(h));
        size_t o = (size_t)(bx + ty + dy * 8) * CDIM + by + tx;
        Thi[o] = h;
        Tlo[o] = l;
    }
}

// v fp32 [ (b*2048+t), h*64+d ] -> vt fp16 hi/lo [hn][d][t]
__global__ void __launch_bounds__(256)
vt_split(const float* __restrict__ v, __half* __restrict__ vthi,
         __half* __restrict__ vtlo)
{
    __shared__ float ts[32][33];
    const int tx = threadIdx.x & 31, ty = threadIdx.x >> 5;
    const int t0 = blockIdx.x << 5;
    const int d0 = blockIdx.y << 5;
    const int hn = blockIdx.z;
    const int b = hn >> 4, h = hn & 15;
    #pragma unroll
    for (int k = 0; k < 4; k++)
        ts[ty + k*8][tx] = v[(size_t)(b*SEQ + t0 + ty + k*8) * CDIM + h*64 + d0 + tx];
    __syncthreads();
    #pragma unroll
    for (int k = 0; k < 4; k++) {
        float val = ts[tx][ty + k*8];
        __half hh = __float2half(val);
        __half ll = __float2half(val - __half2float(hh));
        size_t o = ((size_t)hn * DHEAD + d0 + ty + k*8) * SEQ + t0 + tx;
        vthi[o] = hh;
        vtlo[o] = ll;
    }
}

// ---------------- HMMA attention: scores -----------------------------------
#define SLD   72
#define STILE (128*SLD)
#define SSM_TOTAL (6*STILE*2)

static __device__ __forceinline__ void sc_fill_tile(
    uint32_t dsth, uint32_t dstl,
    const __nv_bfloat16* __restrict__ srch, const __nv_bfloat16* __restrict__ srcl,
    int row0, int tid)
{
    #pragma unroll
    for (int t = 0; t < 8; t++) {
        int i = tid + t * 256;
        int which = i >> 10;
        int e = i & 1023;
        int r = e >> 3, c8 = e & 7;
        const __nv_bfloat16* src = (which ? srcl : srch) + (size_t)(row0 + r)*CDIM + (c8 << 3);
        uint32_t dst = (which ? dstl : dsth) + (r*SLD + (c8 << 3)) * 2;
        cp_async16(dst, src);
    }
    cp_commit();
}

__global__ void __launch_bounds__(256, 1)
attn_scores_hmma(const __nv_bfloat16* __restrict__ qhi, const __nv_bfloat16* __restrict__ qlo,
                 const __nv_bfloat16* __restrict__ khi, const __nv_bfloat16* __restrict__ klo,
                 __half* __restrict__ pexp, float* __restrict__ wts, float* __restrict__ l)
{
    extern __shared__ __nv_bfloat16 sm[];
    __shared__ float red[128][2];
    const uint32_t sb = smem_u32(sm);
    const int tid  = threadIdx.x;
    const int warp = tid >> 5;
    const int lane = tid & 31;
    const int wm = warp & 3, wn = warp >> 2;
    const int lr = lane >> 2, lc = (lane & 3) << 1;

    const int qt = 15 - (blockIdx.x & 15);
    const int hn = blockIdx.x >> 4;
    const int b = hn >> 4, h = hn & 15;
    const int q0 = qt << 7;

    const __nv_bfloat16* gqh = qhi + (size_t)b*SEQ*CDIM + h*64;
    const __nv_bfloat16* gql = qlo + (size_t)b*SEQ*CDIM + h*64;
    const __nv_bfloat16* gkh = khi + (size_t)b*SEQ*CDIM + h*64;
    const __nv_bfloat16* gkl = klo + (size_t)b*SEQ*CDIM + h*64;
    __half* prow = pexp + (size_t)hn * SEQ * SEQ;
    float* wrow = wts + (size_t)hn * SEQ * SEQ;

    const __nv_bfloat16* sQh = sm;
    const __nv_bfloat16* sQl = sm + STILE;
    const uint32_t kbase = sb + 2*STILE*2;

    {
        #pragma unroll
        for (int t = 0; t < 8; t++) {
            int i = tid + t * 256;
            int which = i >> 10, e = i & 1023;
            int r = e >> 3, c8 = e & 7;
            cp_async16(sb + (which ? STILE*2 : 0) + (r*SLD + (c8<<3))*2,
                       (which ? gql : gqh) + (size_t)(q0 + r)*CDIM + (c8<<3));
        }
        sc_fill_tile(kbase, kbase + STILE*2, gkh, gkl, 0, tid);
    }
    if (qt >= 1)
        sc_fill_tile(kbase + 2*STILE*2, kbase + 3*STILE*2, gkh, gkl, 128, tid);

    float psum[4] = {0.f, 0.f, 0.f, 0.f};

    for (int kt = 0; kt <= qt; kt++) {
        if (kt + 1 <= qt) cp_wait<1>(); else cp_wait<0>();
        __syncthreads();

        const __nv_bfloat16* Kh = sm + (2 + 2*(kt & 1)) * STILE;
        const __nv_bfloat16* Kl = Kh + STILE;

        float acc[2][8][4];
        #pragma unroll
        for (int mt = 0; mt < 2; mt++)
            #pragma unroll
            for (int nt = 0; nt < 8; nt++)
                #pragma unroll
                for (int r = 0; r < 4; r++) acc[mt][nt][r] = 0.f;

        #pragma unroll
        for (int ks = 0; ks < 4; ks++) {
            const int kh = ks * 16;
            uint32_t fahi[2][4], falo[2][4];
            #pragma unroll
            for (int mt = 0; mt < 2; mt++) {
                const int r0 = wm*32 + mt*16 + lr;
                const __nv_bfloat16* p0 = sQh + r0*SLD + kh + lc;
                const __nv_bfloat16* p1 = sQl + r0*SLD + kh + lc;
                fahi[mt][0] = *(const uint32_t*)(p0);
                fahi[mt][1] = *(const uint32_t*)(p0 + 8*SLD);
                fahi[mt][2] = *(const uint32_t*)(p0 + 8);
                fahi[mt][3] = *(const uint32_t*)(p0 + 8*SLD + 8);
                falo[mt][0] = *(const uint32_t*)(p1);
                falo[mt][1] = *(const uint32_t*)(p1 + 8*SLD);
                falo[mt][2] = *(const uint32_t*)(p1 + 8);
                falo[mt][3] = *(const uint32_t*)(p1 + 8*SLD + 8);
            }
            #pragma unroll
            for (int nt = 0; nt < 8; nt++) {
                const int nr = wn*64 + nt*8 + lr;
                const __nv_bfloat16* pk0 = Kh + nr*SLD + kh + lc;
                const __nv_bfloat16* pk1 = Kl + nr*SLD + kh + lc;
                uint32_t fbhi[2], fblo[2];
                fbhi[0] = *(const uint32_t*)(pk0);
                fbhi[1] = *(const uint32_t*)(pk0 + 8);
                fblo[0] = *(const uint32_t*)(pk1);
                fblo[1] = *(const uint32_t*)(pk1 + 8);
                #pragma unroll
                for (int mt = 0; mt < 2; mt++) {
                    mma_bf16(acc[mt][nt], fahi[mt], fbhi);
                    mma_bf16(acc[mt][nt], fahi[mt], fblo);
                    mma_bf16(acc[mt][nt], falo[mt], fbhi);
                }
            }
        }

        // epilogue: scale, mask, exp, rowsum, store fp16
        #pragma unroll
        for (int mt = 0; mt < 2; mt++) {
            const int grow0 = q0 + wm*32 + mt*16 + lr;
            const int grow1 = grow0 + 8;
            #pragma unroll
            for (int nt = 0; nt < 8; nt++) {
                const int gcol = (kt << 7) + wn*64 + nt*8 + lc;
                float e00 = (gcol     <= grow0) ? exp_fast(acc[mt][nt][0] * 0.125f) : 0.f;
                float e01 = (gcol + 1 <= grow0) ? exp_fast(acc[mt][nt][1] * 0.125f) : 0.f;
                float e10 = (gcol     <= grow1) ? exp_fast(acc[mt][nt][2] * 0.125f) : 0.f;
                float e11 = (gcol + 1 <= grow1) ? exp_fast(acc[mt][nt][3] * 0.125f) : 0.f;
                psum[mt*2 + 0] += e00 + e01;
                psum[mt*2 + 1] += e10 + e11;
                __half2 p0 = __floats2half2_rn(e00, e01);
                __half2 p1 = __floats2half2_rn(e10, e11);
                *(uint32_t*)(prow + (size_t)grow0*SEQ + gcol) = *(uint32_t*)&p0;
                *(uint32_t*)(prow + (size_t)grow1*SEQ + gcol) = *(uint32_t*)&p1;
            }
        }

        __syncthreads();
        if (kt + 2 <= qt)
            sc_fill_tile(kbase + 2*(kt & 1)*STILE*2, kbase + (2*(kt & 1)+1)*STILE*2,
                         gkh, gkl, (kt + 2) << 7, tid);
    }

    // zero upper triangle of FINAL weights output
    {
        const int c0 = (qt + 1) << 7;
        const int w4 = (SEQ - c0) >> 2;
        if (w4 > 0) {
            float4 z = make_float4(0.f, 0.f, 0.f, 0.f);
            for (int i = tid; i < 128 * w4; i += 256) {
                int r = i / w4, c = (i - r*w4) << 2;
                *(float4*)(wrow + (size_t)(q0 + r)*SEQ + c0 + c) = z;
            }
        }
    }

    #pragma unroll
    for (int t = 0; t < 4; t++) {
        psum[t] += __shfl_xor_sync(0xffffffff, psum[t], 1);
        psum[t] += __shfl_xor_sync(0xffffffff, psum[t], 2);
    }
    if ((lane & 3) == 0) {
        #pragma unroll
        for (int t = 0; t < 4; t++)
            red[wm*32 + (t >> 1)*16 + (t & 1)*8 + lr][wn] = psum[t];
    }
    __syncthreads();
    if (tid < 128) l[hn*SEQ + q0 + tid] = red[tid][0] + red[tid][1];
}

// ---------------- HMMA attention: P @ V (fp16 P from gmem) ------------------
#define VLD   136
#define VTILE (64*VLD)
#define PSM_TOTAL (4*VTILE*2)

static __device__ __forceinline__ void pv_fill_tile(
    uint32_t dsth, uint32_t dstl,
    const __half* __restrict__ srch, const __half* __restrict__ srcl,
    int t0, int tid)
{
    #pragma unroll
    for (int t = 0; t < 8; t++) {
        int i = tid + t * 256;
        int which = i >> 10;
        int e = i & 1023;
        int d = e >> 4, c8 = e & 15;
        const __half* src = (which ? srcl : srch) + (size_t)d*SEQ + t0 + (c8 << 3);
        uint32_t dst = (which ? dstl : dsth) + (d*VLD + (c8 << 3)) * 2;
        cp_async16(dst, src);
    }
    cp_commit();
}

__global__ void __launch_bounds__(256, 1)
attn_pv_hmma(const __half* __restrict__ vthi, const __half* __restrict__ vtlo,
             const __half* __restrict__ pexp, float* __restrict__ wts,
             const float* __restrict__ l,
             __nv_bfloat16* __restrict__ ohi, __nv_bfloat16* __restrict__ olo)
{
    extern __shared__ __half smh[];
    __shared__ float linv[128];
    const uint32_t sb = smem_u32(smh);
    const int tid  = threadIdx.x;
    const int warp = tid >> 5;
    const int lane = tid & 31;
    const int wm = warp & 3, wn = warp >> 2;
    const int lr = lane >> 2, lc = (lane & 3) << 1;

    const int qt = 15 - (blockIdx.x & 15);
    const int hn = blockIdx.x >> 4;
    const int b = hn >> 4, h = hn & 15;
    const int q0 = qt << 7;

    const __half* gvh = vthi + (size_t)hn * DHEAD * SEQ;
    const __half* gvl = vtlo + (size_t)hn * DHEAD * SEQ;
    const __half* prow = pexp + (size_t)hn * SEQ * SEQ;
    float* wrow = wts + (size_t)hn * SEQ * SEQ;

    if (tid < 128) linv[tid] = 1.f / l[hn*SEQ + q0 + tid];

    pv_fill_tile(sb, sb + VTILE*2, gvh, gvl, 0, tid);
    if (qt >= 1) pv_fill_tile(sb + 2*VTILE*2, sb + 3*VTILE*2, gvh, gvl, 128, tid);

    float li[2][2];
    float acc[2][4][4];
    #pragma unroll
    for (int mt = 0; mt < 2; mt++)
        #pragma unroll
        for (int nt = 0; nt < 4; nt++)
            #pragma unroll
            for (int r = 0; r < 4; r++) acc[mt][nt][r] = 0.f;

    for (int kt = 0; kt <= qt; kt++) {
        if (kt + 1 <= qt) cp_wait<1>(); else cp_wait<0>();
        __syncthreads();
        if (kt == 0) {
            #pragma unroll
            for (int mt = 0; mt < 2; mt++) {
                li[mt][0] = linv[wm*32 + mt*16 + lr];
                li[mt][1] = linv[wm*32 + mt*16 + lr + 8];
            }
        }

        const __half* Vh = smh + 2*(kt & 1)*VTILE;
        const __half* Vl = Vh + VTILE;

        #pragma unroll
        for (int ks = 0; ks < 8; ks++) {
            const int gk = (kt << 7) + ks*16;
            uint32_t fp[2][4];
            #pragma unroll
            for (int mt = 0; mt < 2; mt++) {
                const int r0 = q0 + wm*32 + mt*16 + lr;
                const __half* pr0 = prow + (size_t)r0*SEQ + gk + lc;
                const __half* pr1 = prow + (size_t)(r0+8)*SEQ + gk + lc;
                fp[mt][0] = *(const uint32_t*)(pr0);
                fp[mt][1] = *(const uint32_t*)(pr1);
                fp[mt][2] = *(const uint32_t*)(pr0 + 8);
                fp[mt][3] = *(const uint32_t*)(pr1 + 8);

                // write normalized fp32 weights (balance across wn by ks parity)
                if (wn == (ks & 1)) {
                    float2 w00 = __half22float2(*(const __half2*)&fp[mt][0]);
                    float2 w10 = __half22float2(*(const __half2*)&fp[mt][1]);
                    float2 w01 = __half22float2(*(const __half2*)&fp[mt][2]);
                    float2 w11 = __half22float2(*(const __half2*)&fp[mt][3]);
                    w00.x *= li[mt][0]; w00.y *= li[mt][0];
                    w01.x *= li[mt][0]; w01.y *= li[mt][0];
                    w10.x *= li[mt][1]; w10.y *= li[mt][1];
                    w11.x *= li[mt][1]; w11.y *= li[mt][1];
                    *(float2*)(wrow + (size_t)r0*SEQ + gk + lc)         = w00;
                    *(float2*)(wrow + (size_t)r0*SEQ + gk + lc + 8)     = w01;
                    *(float2*)(wrow + (size_t)(r0+8)*SEQ + gk + lc)     = w10;
                    *(float2*)(wrow + (size_t)(r0+8)*SEQ + gk + lc + 8) = w11;
                }
            }
            #pragma unroll
            for (int nt = 0; nt < 4; nt++) {
                const int nr = wn*32 + nt*8 + lr;
                const __half* pv0 = Vh + nr*VLD + ks*16 + lc;
                const __half* pv1 = Vl + nr*VLD + ks*16 + lc;
                uint32_t fbhi[2], fblo[2];
                fbhi[0] = *(const uint32_t*)(pv0);
                fbhi[1] = *(const uint32_t*)(pv0 + 8);
                fblo[0] = *(const uint32_t*)(pv1);
                fblo[1] = *(const uint32_t*)(pv1 + 8);
                #pragma unroll
                for (int mt = 0; mt < 2; mt++) {
                    mma_f16(acc[mt][nt], fp[mt], fbhi);
                    mma_f16(acc[mt][nt], fp[mt], fblo);
                }
            }
        }

        __syncthreads();
        if (kt + 2 <= qt)
            pv_fill_tile(sb + 2*(kt & 1)*VTILE*2, sb + (2*(kt & 1)+1)*VTILE*2,
                         gvh, gvl, (kt + 2) << 7, tid);
    }

    // epilogue: scale by linv, write Wo-GEMM input (bf16 hi/lo)
    #pragma unroll
    for (int mt = 0; mt < 2; mt++) {
        const int grow = q0 + wm*32 + mt*16 + lr;
        #pragma unroll
        for (int nt = 0; nt < 4; nt++) {
            const int d = wn*32 + nt*8 + lc;
            const size_t o0 = (size_t)(b*SEQ + grow) * CDIM + h*64 + d;
            const size_t o1 = (size_t)(b*SEQ + grow + 8) * CDIM + h*64 + d;
            float v[4];
            v[0] = acc[mt][nt][0] * li[mt][0];
            v[1] = acc[mt][nt][1] * li[mt][0];
            v[2] = acc[mt][nt][2] * li[mt][1];
            v[3] = acc[mt][nt][3] * li[mt][1];
            __nv_bfloat16 hh[4], ll[4];
            #pragma unroll
            for (int z = 0; z < 4; z++) {
                hh[z] = __float2bfloat16(v[z]);
                ll[z] = __float2bfloat16(v[z] - __bfloat162float(hh[z]));
            }
            *(__nv_bfloat162*)(ohi + o0) = *(__nv_bfloat162*)&hh[0];
            *(__nv_bfloat162*)(ohi + o1) = *(__nv_bfloat162*)&hh[2];
            *(__nv_bfloat162*)(olo + o0) = *(__nv_bfloat162*)&ll[0];
            *(__nv_bfloat162*)(olo + o1) = *(__nv_bfloat162*)&ll[2];
        }
    }
}

// ---------------------------------------------------------------------------
extern "C" void kernel_launch(void* const* d_in, const int* in_sizes, int n_in,
                              void* d_out, int out_size)
{
    const float* x  = (const float*)d_in[0];
    const float* Wq = (const float*)d_in[1];
    const float* bq = (const float*)d_in[2];
    const float* Wk = (const float*)d_in[3];
    const float* bk = (const float*)d_in[4];
    const float* Wv = (const float*)d_in[5];
    const float* bv = (const float*)d_in[6];
    const float* Wo = (const float*)d_in[7];
    const float* bo = (const float*)d_in[8];

    float* out = (float*)d_out;                 // (B,T,C)
    float* wts = out + (size_t)MR * CDIM;       // (B,N,T,T)

    void *pv, *pl, *pp, *pahi, *palo, *pwhi, *pwlo;
    void *pqhi, *pqlo, *pkhi, *pklo, *pvthi, *pvtlo;
    cudaGetSymbolAddress(&pv, g_v);
    cudaGetSymbolAddress(&pl, g_l);
    cudaGetSymbolAddress(&pp, g_p);
    cudaGetSymbolAddress(&pahi, g_ahi);
    cudaGetSymbolAddress(&palo, g_alo);
    cudaGetSymbolAddress(&pwhi, g_whi);
    cudaGetSymbolAddress(&pwlo, g_wlo);
    cudaGetSymbolAddress(&pqhi, g_qhi);
    cudaGetSymbolAddress(&pqlo, g_qlo);
    cudaGetSymbolAddress(&pkhi, g_khi);
    cudaGetSymbolAddress(&pklo, g_klo);
    cudaGetSymbolAddress(&pvthi, g_vthi);
    cudaGetSymbolAddress(&pvtlo, g_vtlo);

    __nv_bfloat16* ahi = (__nv_bfloat16*)pahi;
    __nv_bfloat16* alo = (__nv_bfloat16*)palo;
    __nv_bfloat16* whi = (__nv_bfloat16*)pwhi;
    __nv_bfloat16* wlo = (__nv_bfloat16*)pwlo;
    const size_t WSZ = (size_t)CDIM * CDIM;

    cudaFuncSetAttribute(gemm_hmma, cudaFuncAttributeMaxDynamicSharedMemorySize, GSM_TOTAL);
    cudaFuncSetAttribute(attn_scores_hmma, cudaFuncAttributeMaxDynamicSharedMemorySize, SSM_TOTAL);
    cudaFuncSetAttribute(attn_pv_hmma, cudaFuncAttributeMaxDynamicSharedMemorySize, PSM_TOTAL);

    dim3 tgrid(CDIM/32, CDIM/32);
    transpose_split<<<tgrid, 256>>>(Wq, whi + 0*WSZ, wlo + 0*WSZ);
    transpose_split<<<tgrid, 256>>>(Wk, whi + 1*WSZ, wlo + 1*WSZ);
    transpose_split<<<tgrid, 256>>>(Wv, whi + 2*WSZ, wlo + 2*WSZ);
    transpose_split<<<tgrid, 256>>>(Wo, whi + 3*WSZ, wlo + 3*WSZ);
    split_f32<<<(int)((size_t)MR*CDIM/4/256), 256>>>(x, ahi, alo);

    dim3 ggrid(CDIM/128, MR/128);
    gemm_hmma<<<ggrid, 256, GSM_TOTAL>>>(ahi, alo, whi + 0*WSZ, wlo + 0*WSZ, bq,
                                          nullptr, (__nv_bfloat16*)pqhi, (__nv_bfloat16*)pqlo);
    gemm_hmma<<<ggrid, 256, GSM_TOTAL>>>(ahi, alo, whi + 1*WSZ, wlo + 1*WSZ, bk,
                                          nullptr, (__nv_bfloat16*)pkhi, (__nv_bfloat16*)pklo);
    gemm_hmma<<<ggrid, 256, GSM_TOTAL>>>(ahi, alo, whi + 2*WSZ, wlo + 2*WSZ, bv,
                                          (float*)pv, nullptr, nullptr);

    dim3 vgrid(SEQ/32, DHEAD/32, BATCH*NHEAD);
    vt_split<<<vgrid, 256>>>((const float*)pv, (__half*)pvthi, (__half*)pvtlo);

    const int ablocks = BATCH*NHEAD*(SEQ/128);  // 1024
    attn_scores_hmma<<<ablocks, 256, SSM_TOTAL>>>(
        (const __nv_bfloat16*)pqhi, (const __nv_bfloat16*)pqlo,
        (const __nv_bfloat16*)pkhi, (const __nv_bfloat16*)pklo,
        (__half*)pp, wts, (float*)pl);
    attn_pv_hmma<<<ablocks, 256, PSM_TOTAL>>>(
        (const __half*)pvthi, (const __half*)pvtlo,
        (const __half*)pp, wts, (const float*)pl, ahi, alo);

    gemm_hmma<<<ggrid, 256, GSM_TOTAL>>>(ahi, alo, whi + 3*WSZ, wlo + 3*WSZ, bo,
                                          out, nullptr, nullptr);
}